// round 9
// baseline (speedup 1.0000x reference)
#include <cuda_runtime.h>
#include <cuda_bf16.h>
#include <math.h>
#include <stdint.h>

#define NN 50000
#define EE 800000
#define HH 128

// ================= scratch (static device globals; no allocation) =================
__device__ float g_deg[NN];
__device__ int   g_indeg[NN];
__device__ int   g_rowptr[NN + 1];
__device__ int   g_cursor[NN];
__device__ int   g_col[EE];
__device__ float g_wgt[EE];

__device__ float g_T1 [(size_t)NN * HH];
__device__ float g_T2 [(size_t)NN * HH];
__device__ float g_T3 [(size_t)NN * HH];
__device__ float g_acc[(size_t)NN * HH];

__device__ float g_q1[NN * 3], g_q2[NN * 3], g_q3[NN * 3];
__device__ float g_sum[HH], g_sumsq[HH];
__device__ float g_bnsc[HH], g_bnsh[HH];   // folded BN: h = sc*acc + sh

// pre-converted bf16 hi/lo weights, padded [n][k] layout:
#define WK_STRIDE 136
#define W_HALF    (HH * WK_STRIDE)            // 17408 bf16
#define W_TERM    (2 * W_HALF)                // 34816 bf16
#define W_LAYER   (4 * W_TERM)                // 139264 bf16
__device__ __nv_bfloat16 g_Wc[3 * W_LAYER];

#define SCB 512
#define NSCB ((NN + SCB - 1) / SCB)
__device__ int g_bsum[NSCB];

// ================= mma.sync helper (sm_80+ HMMA, valid on plain sm_103) ==========
__device__ __forceinline__ void mma16816(float* c, const uint32_t* a,
                                         uint32_t b0, uint32_t b1) {
    asm volatile(
        "mma.sync.aligned.m16n8k16.row.col.f32.bf16.bf16.f32 "
        "{%0,%1,%2,%3}, {%4,%5,%6,%7}, {%8,%9}, {%0,%1,%2,%3};\n"
        : "+f"(c[0]), "+f"(c[1]), "+f"(c[2]), "+f"(c[3])
        : "r"(a[0]), "r"(a[1]), "r"(a[2]), "r"(a[3]), "r"(b0), "r"(b1));
}

// ================= setup kernels =================
__global__ void k_zero() {
    int i = blockIdx.x * blockDim.x + threadIdx.x;
    if (i < NN) { g_deg[i] = 0.f; g_indeg[i] = 0; }
    if (i < HH) { g_sum[i] = 0.f; g_sumsq[i] = 0.f; }
}

__global__ void k_degree(const int* __restrict__ ei) {
    int e = blockIdx.x * blockDim.x + threadIdx.x;
    if (e >= EE) return;
    atomicAdd(&g_deg[ei[e]], 1.0f);
    atomicAdd(&g_indeg[ei[EE + e]], 1);
}

__global__ void k_dinv() {
    int i = blockIdx.x * blockDim.x + threadIdx.x;
    if (i >= NN) return;
    float d = g_deg[i];
    g_deg[i] = (d > 0.f) ? rsqrtf(d) : 0.f;
}

// ---- block-parallel exclusive scan of indeg -> rowptr ----
__global__ void k_bsum() {
    __shared__ int sh[SCB];
    int i = blockIdx.x * SCB + threadIdx.x;
    sh[threadIdx.x] = (i < NN) ? g_indeg[i] : 0;
    __syncthreads();
    for (int off = SCB / 2; off > 0; off >>= 1) {
        if (threadIdx.x < off) sh[threadIdx.x] += sh[threadIdx.x + off];
        __syncthreads();
    }
    if (threadIdx.x == 0) g_bsum[blockIdx.x] = sh[0];
}
__global__ void k_bscan() {
    int acc = 0;
    for (int i = 0; i < NSCB; i++) { int v = g_bsum[i]; g_bsum[i] = acc; acc += v; }
    g_rowptr[NN] = acc;
}
__global__ void k_scanfin() {
    __shared__ int sh[SCB];
    int t = threadIdx.x;
    int i = blockIdx.x * SCB + t;
    int v = (i < NN) ? g_indeg[i] : 0;
    sh[t] = v;
    __syncthreads();
    for (int off = 1; off < SCB; off <<= 1) {
        int add = (t >= off) ? sh[t - off] : 0;
        __syncthreads();
        sh[t] += add;
        __syncthreads();
    }
    if (i < NN) {
        int ex = g_bsum[blockIdx.x] + sh[t] - v;
        g_rowptr[i] = ex;
        g_cursor[i] = ex;
    }
}

__global__ void k_scatter(const int* __restrict__ ei) {
    int e = blockIdx.x * blockDim.x + threadIdx.x;
    if (e >= EE) return;
    int s = ei[e];
    int d = ei[EE + e];
    float w = -g_deg[s] * g_deg[d];
    int pos = atomicAdd(&g_cursor[d], 1);
    g_col[pos] = s;
    g_wgt[pos] = w;
}

// ---- W conversion: fp32 W[t][k][n] -> bf16 hi/lo [t][n][k] (stride 136) ----
__global__ void k_wconv(const float* __restrict__ W, __nv_bfloat16* __restrict__ dst) {
    int idx = blockIdx.x * blockDim.x + threadIdx.x;
    if (idx >= 4 * 16384) return;
    int t = idx >> 14;
    int rem = idx & 16383;
    int n = rem >> 7;
    int k = rem & 127;
    float v = W[(t << 14) + (k << 7) + n];
    __nv_bfloat16 hi = __float2bfloat16(v);
    __nv_bfloat16 lo = __float2bfloat16(v - __bfloat162float(hi));
    __nv_bfloat16* base = dst + (size_t)t * W_TERM + n * WK_STRIDE + k;
    base[0] = hi;
    base[W_HALF] = lo;
}

// ================= propagation (optional inline BN on gather src / sub) ==========
__global__ void k_prop128(const float* __restrict__ t, const float* __restrict__ sub,
                          float* __restrict__ out, float scale, float beta,
                          int bn_src, int bn_sub) {
    int gw = (blockIdx.x * blockDim.x + threadIdx.x) >> 5;
    int lane = threadIdx.x & 31;
    if (gw >= NN) return;
    float4 sc = make_float4(1.f, 1.f, 1.f, 1.f);
    float4 sh = make_float4(0.f, 0.f, 0.f, 0.f);
    if (bn_src | bn_sub) {
        sc = *(const float4*)&g_bnsc[lane * 4];
        sh = *(const float4*)&g_bnsh[lane * 4];
    }
    int beg = g_rowptr[gw], end = g_rowptr[gw + 1];
    float ax = 0.f, ay = 0.f, az = 0.f, aw = 0.f, w0s = 0.f;
    float bx = 0.f, by = 0.f, bz = 0.f, bw = 0.f, w1s = 0.f;
    int e = beg;
    for (; e + 2 <= end; e += 2) {
        int s0 = __ldg(&g_col[e]);     float u0 = __ldg(&g_wgt[e]);
        int s1 = __ldg(&g_col[e + 1]); float u1 = __ldg(&g_wgt[e + 1]);
        float4 v0 = *(const float4*)&t[(size_t)s0 * HH + lane * 4];
        float4 v1 = *(const float4*)&t[(size_t)s1 * HH + lane * 4];
        ax += u0 * v0.x; ay += u0 * v0.y; az += u0 * v0.z; aw += u0 * v0.w; w0s += u0;
        bx += u1 * v1.x; by += u1 * v1.y; bz += u1 * v1.z; bw += u1 * v1.w; w1s += u1;
    }
    if (e < end) {
        int s0 = __ldg(&g_col[e]); float u0 = __ldg(&g_wgt[e]);
        float4 v0 = *(const float4*)&t[(size_t)s0 * HH + lane * 4];
        ax += u0 * v0.x; ay += u0 * v0.y; az += u0 * v0.z; aw += u0 * v0.w; w0s += u0;
    }
    ax += bx; ay += by; az += bz; aw += bw;
    float sumw = w0s + w1s;
    if (bn_src) {
        ax = sc.x * ax + sh.x * sumw;
        ay = sc.y * ay + sh.y * sumw;
        az = sc.z * az + sh.z * sumw;
        aw = sc.w * aw + sh.w * sumw;
    }
    float4 r;
    if (beta != 0.f) {
        float4 sv = *(const float4*)&sub[(size_t)gw * HH + lane * 4];
        if (bn_sub) {
            sv.x = sc.x * sv.x + sh.x;
            sv.y = sc.y * sv.y + sh.y;
            sv.z = sc.z * sv.z + sh.z;
            sv.w = sc.w * sv.w + sh.w;
        }
        r.x = scale * ax + beta * sv.x;
        r.y = scale * ay + beta * sv.y;
        r.z = scale * az + beta * sv.z;
        r.w = scale * aw + beta * sv.w;
    } else {
        r.x = scale * ax; r.y = scale * ay; r.z = scale * az; r.w = scale * aw;
    }
    *(float4*)&out[(size_t)gw * HH + lane * 4] = r;
}

__global__ void k_prop3(const float* __restrict__ t, const float* __restrict__ sub,
                        float* __restrict__ out, float scale, float beta) {
    int i = blockIdx.x * blockDim.x + threadIdx.x;
    if (i >= NN) return;
    int beg = g_rowptr[i], end = g_rowptr[i + 1];
    float a0 = 0.f, a1 = 0.f, a2 = 0.f;
    for (int e = beg; e < end; e++) {
        int s = g_col[e];
        float w = g_wgt[e];
        a0 += w * t[s * 3 + 0];
        a1 += w * t[s * 3 + 1];
        a2 += w * t[s * 3 + 2];
    }
    if (beta != 0.f) {
        out[i * 3 + 0] = scale * a0 + beta * sub[i * 3 + 0];
        out[i * 3 + 1] = scale * a1 + beta * sub[i * 3 + 1];
        out[i * 3 + 2] = scale * a2 + beta * sub[i * 3 + 2];
    } else {
        out[i * 3 + 0] = scale * a0;
        out[i * 3 + 1] = scale * a1;
        out[i * 3 + 2] = scale * a2;
    }
}

// ================= layer 1 (3->128) SIMT, stats fused =================
#define L1_ROWS 64
__global__ void k_layer1(const float* __restrict__ x,
                         const float* __restrict__ W1, const float* __restrict__ b1) {
    __shared__ float w[4 * 3 * HH];
    __shared__ float bb[HH];
    for (int i = threadIdx.x; i < 4 * 3 * HH; i += blockDim.x) w[i] = W1[i];
    if (threadIdx.x < HH) bb[threadIdx.x] = b1[threadIdx.x];
    __syncthreads();
    int h = threadIdx.x;
    int row0 = blockIdx.x * L1_ROWS;
    float s = 0.f, sq = 0.f;
    for (int r = 0; r < L1_ROWS; r++) {
        int i = row0 + r;
        if (i >= NN) break;
        float acc = bb[h];
        #pragma unroll
        for (int c = 0; c < 3; c++) {
            acc += x[i * 3 + c]    * w[(0 * 3 + c) * HH + h];
            acc += g_q1[i * 3 + c] * w[(1 * 3 + c) * HH + h];
            acc += g_q2[i * 3 + c] * w[(2 * 3 + c) * HH + h];
            acc += g_q3[i * 3 + c] * w[(3 * 3 + c) * HH + h];
        }
        float y = (acc > 0.f) ? acc : 0.01f * acc;
        g_acc[(size_t)i * HH + h] = y;
        s += y; sq += y * y;
    }
    atomicAdd(&g_sum[h], s);
    atomicAdd(&g_sumsq[h], sq);
}

// ================= BN finalize: fold (m, rstd, gamma, beta) -> sc/sh =============
__global__ void k_bnfin(const float* __restrict__ gam, const float* __restrict__ bet) {
    int h = threadIdx.x;   // 128 threads, 1 block
    float m = g_sum[h] * (1.0f / NN);
    float v = g_sumsq[h] * (1.0f / NN) - m * m;
    float r = rsqrtf(v + 1e-5f);
    float sc = gam[h] * r;
    g_bnsc[h] = sc;
    g_bnsh[h] = bet[h] - m * sc;
    g_sum[h] = 0.f;
    g_sumsq[h] = 0.f;
}

// ================= mma.sync split-bf16 4-term GEMM =================
// C = act( BN(T0)@W0 + T1@W1 + T2@W2 + T3@W3 + bias ), stats fused if bias.
#define SM_AHI 0
#define SM_ALO (SM_AHI + W_HALF)
#define SM_BHI (SM_ALO + W_HALF)
#define SM_BLO (SM_BHI + W_HALF)
#define SMEM_BF ((size_t)(SM_BLO + W_HALF))            // 69632 bf16
#define SMEM_BYTES (SMEM_BF * 2)                       // 139264 bytes

__global__ void __launch_bounds__(256, 1)
k_mgemm(const float* __restrict__ T0, const float* __restrict__ T1,
        const float* __restrict__ T2, const float* __restrict__ T3,
        const __nv_bfloat16* __restrict__ Wc,
        float* __restrict__ C, const float* __restrict__ bias, float slope) {
    extern __shared__ __nv_bfloat16 sm[];
    int tid = threadIdx.x;
    int wid = tid >> 5, lane = tid & 31;
    int gid = lane >> 2, qid = lane & 3;
    int wm = wid & 3, wn = wid >> 2;
    int row0 = blockIdx.x * 128;

    float acc[2][8][4];
    #pragma unroll
    for (int i = 0; i < 2; i++)
        #pragma unroll
        for (int j = 0; j < 8; j++)
            #pragma unroll
            for (int q = 0; q < 4; q++) acc[i][j][q] = 0.f;

    const float* Ts[4] = {T0, T1, T2, T3};
    for (int t = 0; t < 4; t++) {
        const float* T = Ts[t];
        for (int q = tid; q < 4096; q += 256) {
            int r = q >> 5;
            int c = (q & 31) << 2;
            int gi = row0 + r;
            float4 v = make_float4(0.f, 0.f, 0.f, 0.f);
            if (gi < NN) v = *(const float4*)&T[(size_t)gi * HH + c];
            if (t == 0) {   // T0 = BN(acc): apply folded scale/shift per channel
                float4 s4 = *(const float4*)&g_bnsc[c];
                float4 h4 = *(const float4*)&g_bnsh[c];
                v.x = v.x * s4.x + h4.x; v.y = v.y * s4.y + h4.y;
                v.z = v.z * s4.z + h4.z; v.w = v.w * s4.w + h4.w;
            }
            __nv_bfloat16 hx = __float2bfloat16(v.x), hy = __float2bfloat16(v.y);
            __nv_bfloat16 hz = __float2bfloat16(v.z), hw = __float2bfloat16(v.w);
            int o = r * WK_STRIDE + c;
            sm[SM_AHI + o + 0] = hx; sm[SM_AHI + o + 1] = hy;
            sm[SM_AHI + o + 2] = hz; sm[SM_AHI + o + 3] = hw;
            sm[SM_ALO + o + 0] = __float2bfloat16(v.x - __bfloat162float(hx));
            sm[SM_ALO + o + 1] = __float2bfloat16(v.y - __bfloat162float(hy));
            sm[SM_ALO + o + 2] = __float2bfloat16(v.z - __bfloat162float(hz));
            sm[SM_ALO + o + 3] = __float2bfloat16(v.w - __bfloat162float(hw));
        }
        {
            const int4* src = (const int4*)(Wc + (size_t)t * W_TERM);
            int4* dst = (int4*)(sm + SM_BHI);
            for (int q = tid; q < (2 * W_HALF * 2) / 16; q += 256) dst[q] = src[q];
        }
        __syncthreads();

        #pragma unroll
        for (int pass = 0; pass < 3; pass++) {
            const __nv_bfloat16* Ab = sm + ((pass == 2) ? SM_ALO : SM_AHI);
            const __nv_bfloat16* Bb = sm + ((pass == 1) ? SM_BLO : SM_BHI);
            #pragma unroll
            for (int ks = 0; ks < 8; ks++) {
                int k0 = ks * 16;
                uint32_t a[2][4];
                #pragma unroll
                for (int mt = 0; mt < 2; mt++) {
                    int r = wm * 32 + mt * 16 + gid;
                    a[mt][0] = *(const uint32_t*)&Ab[(r    ) * WK_STRIDE + k0     + qid * 2];
                    a[mt][1] = *(const uint32_t*)&Ab[(r + 8) * WK_STRIDE + k0     + qid * 2];
                    a[mt][2] = *(const uint32_t*)&Ab[(r    ) * WK_STRIDE + k0 + 8 + qid * 2];
                    a[mt][3] = *(const uint32_t*)&Ab[(r + 8) * WK_STRIDE + k0 + 8 + qid * 2];
                }
                #pragma unroll
                for (int nt = 0; nt < 8; nt++) {
                    int n = wn * 64 + nt * 8 + gid;
                    uint32_t b0 = *(const uint32_t*)&Bb[n * WK_STRIDE + k0     + qid * 2];
                    uint32_t b1 = *(const uint32_t*)&Bb[n * WK_STRIDE + k0 + 8 + qid * 2];
                    mma16816(acc[0][nt], a[0], b0, b1);
                    mma16816(acc[1][nt], a[1], b0, b1);
                }
            }
        }
        __syncthreads();
    }

    // --- epilogue: bias + activation + fused BN stats ---
    float* ssum = (float*)sm;          // [0:128) sum, [128:256) sumsq
    if (bias) {
        ssum[tid] = 0.f;               // blockDim == 256
        __syncthreads();
    }
    float scol[8][2], sqcol[8][2];
    #pragma unroll
    for (int nt = 0; nt < 8; nt++) {
        scol[nt][0] = 0.f; scol[nt][1] = 0.f;
        sqcol[nt][0] = 0.f; sqcol[nt][1] = 0.f;
    }
    #pragma unroll
    for (int mt = 0; mt < 2; mt++) {
        int r0 = row0 + wm * 32 + mt * 16 + gid;
        #pragma unroll
        for (int nt = 0; nt < 8; nt++) {
            int col = wn * 64 + nt * 8 + qid * 2;
            float c0 = acc[mt][nt][0], c1 = acc[mt][nt][1];
            float c2 = acc[mt][nt][2], c3 = acc[mt][nt][3];
            if (bias) {
                float bv0 = bias[col], bv1 = bias[col + 1];
                c0 += bv0; c0 = (c0 > 0.f) ? c0 : slope * c0;
                c1 += bv1; c1 = (c1 > 0.f) ? c1 : slope * c1;
                c2 += bv0; c2 = (c2 > 0.f) ? c2 : slope * c2;
                c3 += bv1; c3 = (c3 > 0.f) ? c3 : slope * c3;
                if (r0 < NN) {
                    scol[nt][0] += c0; sqcol[nt][0] += c0 * c0;
                    scol[nt][1] += c1; sqcol[nt][1] += c1 * c1;
                }
                if (r0 + 8 < NN) {
                    scol[nt][0] += c2; sqcol[nt][0] += c2 * c2;
                    scol[nt][1] += c3; sqcol[nt][1] += c3 * c3;
                }
            }
            if (r0 < NN)     *(float2*)&C[(size_t)r0 * HH + col]       = make_float2(c0, c1);
            if (r0 + 8 < NN) *(float2*)&C[(size_t)(r0 + 8) * HH + col] = make_float2(c2, c3);
        }
    }
    if (bias) {
        #pragma unroll
        for (int nt = 0; nt < 8; nt++) {
            #pragma unroll
            for (int j = 0; j < 2; j++) {
                float s = scol[nt][j], q = sqcol[nt][j];
                #pragma unroll
                for (int off = 4; off < 32; off <<= 1) {   // reduce across gid
                    s += __shfl_xor_sync(0xFFFFFFFFu, s, off);
                    q += __shfl_xor_sync(0xFFFFFFFFu, q, off);
                }
                if (lane < 4) {
                    int col = wn * 64 + nt * 8 + qid * 2 + j;
                    atomicAdd(&ssum[col], s);
                    atomicAdd(&ssum[128 + col], q);
                }
            }
        }
        __syncthreads();
        if (tid < 128) atomicAdd(&g_sum[tid], ssum[tid]);
        else           atomicAdd(&g_sumsq[tid - 128], ssum[tid]);
    }
}

// ================= final: +b4, L2-normalize, project 128->3 =================
__global__ void k_final(const float* __restrict__ b4, const float* __restrict__ Wm,
                        const float* __restrict__ bm, float* __restrict__ out) {
    __shared__ float wm[HH * 3];
    __shared__ float bb[HH];
    __shared__ float bmv[3];
    for (int i = threadIdx.x; i < HH * 3; i += blockDim.x) wm[i] = Wm[i];
    if (threadIdx.x < HH) bb[threadIdx.x] = b4[threadIdx.x];
    if (threadIdx.x < 3) bmv[threadIdx.x] = bm[threadIdx.x];
    __syncthreads();
    int gw = (blockIdx.x * blockDim.x + threadIdx.x) >> 5;
    int lane = threadIdx.x & 31;
    if (gw >= NN) return;
    float4 v = *(const float4*)&g_acc[(size_t)gw * HH + lane * 4];
    v.x += bb[lane * 4 + 0]; v.y += bb[lane * 4 + 1];
    v.z += bb[lane * 4 + 2]; v.w += bb[lane * 4 + 3];
    float sq = v.x * v.x + v.y * v.y + v.z * v.z + v.w * v.w;
    #pragma unroll
    for (int off = 16; off; off >>= 1) sq += __shfl_xor_sync(0xFFFFFFFFu, sq, off);
    float inv = 1.0f / fmaxf(sqrtf(sq), 1e-12f);
    v.x *= inv; v.y *= inv; v.z *= inv; v.w *= inv;
    float o0 = 0.f, o1 = 0.f, o2 = 0.f;
    float vv[4] = {v.x, v.y, v.z, v.w};
    #pragma unroll
    for (int t = 0; t < 4; t++) {
        int h = lane * 4 + t;
        o0 += vv[t] * wm[h * 3 + 0];
        o1 += vv[t] * wm[h * 3 + 1];
        o2 += vv[t] * wm[h * 3 + 2];
    }
    #pragma unroll
    for (int off = 16; off; off >>= 1) {
        o0 += __shfl_xor_sync(0xFFFFFFFFu, o0, off);
        o1 += __shfl_xor_sync(0xFFFFFFFFu, o1, off);
        o2 += __shfl_xor_sync(0xFFFFFFFFu, o2, off);
    }
    if (lane == 0) {
        out[gw * 3 + 0] = o0 + bmv[0];
        out[gw * 3 + 1] = o1 + bmv[1];
        out[gw * 3 + 2] = o2 + bmv[2];
    }
}

// ================= host =================
static inline int GB(long long n, int b) { return (int)((n + b - 1) / b); }

extern "C" void kernel_launch(void* const* d_in, const int* in_sizes, int n_in,
                              void* d_out, int out_size) {
    const float* x   = (const float*)d_in[0];
    const int*   ei  = (const int*)  d_in[1];
    const float* W1  = (const float*)d_in[2];  const float* b1  = (const float*)d_in[3];
    const float* W2  = (const float*)d_in[4];  const float* b2  = (const float*)d_in[5];
    const float* W3  = (const float*)d_in[6];  const float* b3  = (const float*)d_in[7];
    const float* W4  = (const float*)d_in[8];  const float* b4  = (const float*)d_in[9];
    const float* gm1 = (const float*)d_in[10]; const float* be1 = (const float*)d_in[11];
    const float* gm2 = (const float*)d_in[12]; const float* be2 = (const float*)d_in[13];
    const float* gm3 = (const float*)d_in[14]; const float* be3 = (const float*)d_in[15];
    const float* Wm  = (const float*)d_in[16]; const float* bm  = (const float*)d_in[17];
    float* out = (float*)d_out;

    float *p_T1, *p_T2, *p_T3, *p_acc, *p_q1, *p_q2, *p_q3;
    __nv_bfloat16* p_Wc;
    cudaGetSymbolAddress((void**)&p_T1,  g_T1);
    cudaGetSymbolAddress((void**)&p_T2,  g_T2);
    cudaGetSymbolAddress((void**)&p_T3,  g_T3);
    cudaGetSymbolAddress((void**)&p_acc, g_acc);
    cudaGetSymbolAddress((void**)&p_q1,  g_q1);
    cudaGetSymbolAddress((void**)&p_q2,  g_q2);
    cudaGetSymbolAddress((void**)&p_q3,  g_q3);
    cudaGetSymbolAddress((void**)&p_Wc,  g_Wc);

    cudaFuncSetAttribute(k_mgemm, cudaFuncAttributeMaxDynamicSharedMemorySize,
                         (int)SMEM_BYTES);

    // --- graph setup ---
    k_zero   <<<GB(NN, 256), 256>>>();
    k_degree <<<GB(EE, 256), 256>>>(ei);
    k_dinv   <<<GB(NN, 256), 256>>>();
    k_bsum   <<<NSCB, SCB>>>();
    k_bscan  <<<1, 1>>>();
    k_scanfin<<<NSCB, SCB>>>();
    k_scatter<<<GB(EE, 256), 256>>>(ei);
    k_wconv  <<<GB(4 * 16384, 256), 256>>>(W2, p_Wc);
    k_wconv  <<<GB(4 * 16384, 256), 256>>>(W3, p_Wc + W_LAYER);
    k_wconv  <<<GB(4 * 16384, 256), 256>>>(W4, p_Wc + 2 * W_LAYER);

    // --- layer 1 (3 -> 128), leaky_relu; stats fused; BN folded into sc/sh ---
    k_prop3<<<GB(NN, 256), 256>>>(x,    x,    p_q1, 1.f,  0.f);
    k_prop3<<<GB(NN, 256), 256>>>(p_q1, x,    p_q2, 2.f, -1.f);
    k_prop3<<<GB(NN, 256), 256>>>(p_q2, p_q1, p_q3, 2.f, -1.f);
    k_layer1<<<GB(NN, L1_ROWS), 128>>>(x, W1, b1);
    k_bnfin<<<1, 128>>>(gm1, be1);

    const int propBlocks = GB((long long)NN * 32, 256);
    const int gemmBlocks = GB(NN, 128);

    // --- layer 2 (128 -> 128), leaky_relu + BN ---
    k_prop128<<<propBlocks, 256>>>(p_acc, p_acc, p_T1, 1.f,  0.f, 1, 0);
    k_prop128<<<propBlocks, 256>>>(p_T1,  p_acc, p_T2, 2.f, -1.f, 0, 1);
    k_prop128<<<propBlocks, 256>>>(p_T2,  p_T1,  p_T3, 2.f, -1.f, 0, 0);
    k_mgemm<<<gemmBlocks, 256, SMEM_BYTES>>>(p_acc, p_T1, p_T2, p_T3, p_Wc, p_acc, b2, 0.01f);
    k_bnfin<<<1, 128>>>(gm2, be2);

    // --- layer 3 (128 -> 128), relu + BN ---
    k_prop128<<<propBlocks, 256>>>(p_acc, p_acc, p_T1, 1.f,  0.f, 1, 0);
    k_prop128<<<propBlocks, 256>>>(p_T1,  p_acc, p_T2, 2.f, -1.f, 0, 1);
    k_prop128<<<propBlocks, 256>>>(p_T2,  p_T1,  p_T3, 2.f, -1.f, 0, 0);
    k_mgemm<<<gemmBlocks, 256, SMEM_BYTES>>>(p_acc, p_T1, p_T2, p_T3, p_Wc + W_LAYER, p_acc, b3, 0.0f);
    k_bnfin<<<1, 128>>>(gm3, be3);

    // --- layer 4 (128 -> 128), then normalize + project ---
    k_prop128<<<propBlocks, 256>>>(p_acc, p_acc, p_T1, 1.f,  0.f, 1, 0);
    k_prop128<<<propBlocks, 256>>>(p_T1,  p_acc, p_T2, 2.f, -1.f, 0, 1);
    k_prop128<<<propBlocks, 256>>>(p_T2,  p_T1,  p_T3, 2.f, -1.f, 0, 0);
    k_mgemm<<<gemmBlocks, 256, SMEM_BYTES>>>(p_acc, p_T1, p_T2, p_T3, p_Wc + 2 * W_LAYER, p_acc,
                                             (const float*)nullptr, 0.0f);
    k_final<<<GB((long long)NN * 32, 256), 256>>>(b4, Wm, bm, out);
}

// round 10
// speedup vs baseline: 1.0957x; 1.0957x over previous
#include <cuda_runtime.h>
#include <cuda_bf16.h>
#include <math.h>
#include <stdint.h>

#define NN 50000
#define EE 800000
#define HH 128

// ================= scratch (static device globals; no allocation) =================
__device__ float g_deg[NN];
__device__ int   g_indeg[NN];
__device__ int   g_rowptr[NN + 1];
__device__ int   g_cursor[NN];
__device__ int   g_col[EE];
__device__ float g_wgt[EE];

__device__ float g_T1 [(size_t)NN * HH];
__device__ float g_T2 [(size_t)NN * HH];
__device__ float g_T3 [(size_t)NN * HH];
__device__ float g_acc[(size_t)NN * HH];

__device__ float g_q1[NN * 3], g_q2[NN * 3], g_q3[NN * 3];
__device__ float g_sum[HH], g_sumsq[HH];
__device__ float g_bnsc[HH], g_bnsh[HH];   // folded BN: h = sc*acc + sh

// pre-converted bf16 hi/lo weights, padded [n][k] layout:
#define WK_STRIDE 136
#define W_HALF    (HH * WK_STRIDE)            // 17408 bf16
#define W_TERM    (2 * W_HALF)                // 34816 bf16
#define W_LAYER   (4 * W_TERM)                // 139264 bf16
__device__ __nv_bfloat16 g_Wc[3 * W_LAYER];

#define SCB 512
#define NSCB ((NN + SCB - 1) / SCB)
__device__ int g_bsum[NSCB];

// ================= mma.sync helper (sm_80+ HMMA, valid on plain sm_103) ==========
__device__ __forceinline__ void mma16816(float* c, const uint32_t* a,
                                         uint32_t b0, uint32_t b1) {
    asm volatile(
        "mma.sync.aligned.m16n8k16.row.col.f32.bf16.bf16.f32 "
        "{%0,%1,%2,%3}, {%4,%5,%6,%7}, {%8,%9}, {%0,%1,%2,%3};\n"
        : "+f"(c[0]), "+f"(c[1]), "+f"(c[2]), "+f"(c[3])
        : "r"(a[0]), "r"(a[1]), "r"(a[2]), "r"(a[3]), "r"(b0), "r"(b1));
}

// ================= setup kernels =================
__global__ void k_zero() {
    int i = blockIdx.x * blockDim.x + threadIdx.x;
    if (i < NN) { g_deg[i] = 0.f; g_indeg[i] = 0; }
    if (i < HH) { g_sum[i] = 0.f; g_sumsq[i] = 0.f; }
}

__global__ void k_degree(const int* __restrict__ ei) {
    int e = blockIdx.x * blockDim.x + threadIdx.x;
    if (e >= EE) return;
    atomicAdd(&g_deg[ei[e]], 1.0f);
    atomicAdd(&g_indeg[ei[EE + e]], 1);
}

__global__ void k_dinv() {
    int i = blockIdx.x * blockDim.x + threadIdx.x;
    if (i >= NN) return;
    float d = g_deg[i];
    g_deg[i] = (d > 0.f) ? rsqrtf(d) : 0.f;
}

// ---- block-parallel exclusive scan of indeg -> rowptr ----
__global__ void k_bsum() {
    __shared__ int sh[SCB];
    int i = blockIdx.x * SCB + threadIdx.x;
    sh[threadIdx.x] = (i < NN) ? g_indeg[i] : 0;
    __syncthreads();
    for (int off = SCB / 2; off > 0; off >>= 1) {
        if (threadIdx.x < off) sh[threadIdx.x] += sh[threadIdx.x + off];
        __syncthreads();
    }
    if (threadIdx.x == 0) g_bsum[blockIdx.x] = sh[0];
}
__global__ void k_bscan() {
    int acc = 0;
    for (int i = 0; i < NSCB; i++) { int v = g_bsum[i]; g_bsum[i] = acc; acc += v; }
    g_rowptr[NN] = acc;
}
__global__ void k_scanfin() {
    __shared__ int sh[SCB];
    int t = threadIdx.x;
    int i = blockIdx.x * SCB + t;
    int v = (i < NN) ? g_indeg[i] : 0;
    sh[t] = v;
    __syncthreads();
    for (int off = 1; off < SCB; off <<= 1) {
        int add = (t >= off) ? sh[t - off] : 0;
        __syncthreads();
        sh[t] += add;
        __syncthreads();
    }
    if (i < NN) {
        int ex = g_bsum[blockIdx.x] + sh[t] - v;
        g_rowptr[i] = ex;
        g_cursor[i] = ex;
    }
}

__global__ void k_scatter(const int* __restrict__ ei) {
    int e = blockIdx.x * blockDim.x + threadIdx.x;
    if (e >= EE) return;
    int s = ei[e];
    int d = ei[EE + e];
    float w = -g_deg[s] * g_deg[d];
    int pos = atomicAdd(&g_cursor[d], 1);
    g_col[pos] = s;
    g_wgt[pos] = w;
}

// ---- W conversion: fp32 W[t][k][n] -> bf16 hi/lo [t][n][k] (stride 136) ----
__global__ void k_wconv(const float* __restrict__ W, __nv_bfloat16* __restrict__ dst) {
    int idx = blockIdx.x * blockDim.x + threadIdx.x;
    if (idx >= 4 * 16384) return;
    int t = idx >> 14;
    int rem = idx & 16383;
    int n = rem >> 7;
    int k = rem & 127;
    float v = W[(t << 14) + (k << 7) + n];
    __nv_bfloat16 hi = __float2bfloat16(v);
    __nv_bfloat16 lo = __float2bfloat16(v - __bfloat162float(hi));
    __nv_bfloat16* base = dst + (size_t)t * W_TERM + n * WK_STRIDE + k;
    base[0] = hi;
    base[W_HALF] = lo;
}

// ================= propagation (optional inline BN on gather src / sub) ==========
// Single-edge inner loop (MLP_p1 kept low to avoid cross-CTA L1tex-queue spread).
__global__ void k_prop128(const float* __restrict__ t, const float* __restrict__ sub,
                          float* __restrict__ out, float scale, float beta,
                          int bn_src, int bn_sub) {
    int gw = (blockIdx.x * blockDim.x + threadIdx.x) >> 5;
    int lane = threadIdx.x & 31;
    if (gw >= NN) return;
    float4 sc = make_float4(1.f, 1.f, 1.f, 1.f);
    float4 sh = make_float4(0.f, 0.f, 0.f, 0.f);
    if (bn_src | bn_sub) {
        sc = *(const float4*)&g_bnsc[lane * 4];
        sh = *(const float4*)&g_bnsh[lane * 4];
    }
    int beg = g_rowptr[gw], end = g_rowptr[gw + 1];
    float ax = 0.f, ay = 0.f, az = 0.f, aw = 0.f, ws = 0.f;
    for (int e = beg; e < end; e++) {
        int s = __ldg(&g_col[e]);
        float w = __ldg(&g_wgt[e]);
        float4 v = *(const float4*)&t[(size_t)s * HH + lane * 4];
        ax += w * v.x; ay += w * v.y; az += w * v.z; aw += w * v.w;
        ws += w;
    }
    if (bn_src) {
        ax = sc.x * ax + sh.x * ws;
        ay = sc.y * ay + sh.y * ws;
        az = sc.z * az + sh.z * ws;
        aw = sc.w * aw + sh.w * ws;
    }
    float4 r;
    if (beta != 0.f) {
        float4 sv = *(const float4*)&sub[(size_t)gw * HH + lane * 4];
        if (bn_sub) {
            sv.x = sc.x * sv.x + sh.x;
            sv.y = sc.y * sv.y + sh.y;
            sv.z = sc.z * sv.z + sh.z;
            sv.w = sc.w * sv.w + sh.w;
        }
        r.x = scale * ax + beta * sv.x;
        r.y = scale * ay + beta * sv.y;
        r.z = scale * az + beta * sv.z;
        r.w = scale * aw + beta * sv.w;
    } else {
        r.x = scale * ax; r.y = scale * ay; r.z = scale * az; r.w = scale * aw;
    }
    *(float4*)&out[(size_t)gw * HH + lane * 4] = r;
}

__global__ void k_prop3(const float* __restrict__ t, const float* __restrict__ sub,
                        float* __restrict__ out, float scale, float beta) {
    int i = blockIdx.x * blockDim.x + threadIdx.x;
    if (i >= NN) return;
    int beg = g_rowptr[i], end = g_rowptr[i + 1];
    float a0 = 0.f, a1 = 0.f, a2 = 0.f;
    for (int e = beg; e < end; e++) {
        int s = g_col[e];
        float w = g_wgt[e];
        a0 += w * t[s * 3 + 0];
        a1 += w * t[s * 3 + 1];
        a2 += w * t[s * 3 + 2];
    }
    if (beta != 0.f) {
        out[i * 3 + 0] = scale * a0 + beta * sub[i * 3 + 0];
        out[i * 3 + 1] = scale * a1 + beta * sub[i * 3 + 1];
        out[i * 3 + 2] = scale * a2 + beta * sub[i * 3 + 2];
    } else {
        out[i * 3 + 0] = scale * a0;
        out[i * 3 + 1] = scale * a1;
        out[i * 3 + 2] = scale * a2;
    }
}

// ================= layer 1 (3->128) SIMT, stats fused =================
#define L1_ROWS 64
__global__ void k_layer1(const float* __restrict__ x,
                         const float* __restrict__ W1, const float* __restrict__ b1) {
    __shared__ float w[4 * 3 * HH];
    __shared__ float bb[HH];
    for (int i = threadIdx.x; i < 4 * 3 * HH; i += blockDim.x) w[i] = W1[i];
    if (threadIdx.x < HH) bb[threadIdx.x] = b1[threadIdx.x];
    __syncthreads();
    int h = threadIdx.x;
    int row0 = blockIdx.x * L1_ROWS;
    float s = 0.f, sq = 0.f;
    for (int r = 0; r < L1_ROWS; r++) {
        int i = row0 + r;
        if (i >= NN) break;
        float acc = bb[h];
        #pragma unroll
        for (int c = 0; c < 3; c++) {
            acc += x[i * 3 + c]    * w[(0 * 3 + c) * HH + h];
            acc += g_q1[i * 3 + c] * w[(1 * 3 + c) * HH + h];
            acc += g_q2[i * 3 + c] * w[(2 * 3 + c) * HH + h];
            acc += g_q3[i * 3 + c] * w[(3 * 3 + c) * HH + h];
        }
        float y = (acc > 0.f) ? acc : 0.01f * acc;
        g_acc[(size_t)i * HH + h] = y;
        s += y; sq += y * y;
    }
    atomicAdd(&g_sum[h], s);
    atomicAdd(&g_sumsq[h], sq);
}

// ================= BN finalize: fold (m, rstd, gamma, beta) -> sc/sh =============
__global__ void k_bnfin(const float* __restrict__ gam, const float* __restrict__ bet) {
    int h = threadIdx.x;   // 128 threads, 1 block
    float m = g_sum[h] * (1.0f / NN);
    float v = g_sumsq[h] * (1.0f / NN) - m * m;
    float r = rsqrtf(v + 1e-5f);
    float sc = gam[h] * r;
    g_bnsc[h] = sc;
    g_bnsh[h] = bet[h] - m * sc;
    g_sum[h] = 0.f;
    g_sumsq[h] = 0.f;
}

// ================= mma.sync split-bf16 4-term GEMM =================
// C = act( BN(T0)@W0 + T1@W1 + T2@W2 + T3@W3 + bias ), stats fused if bias.
#define SM_AHI 0
#define SM_ALO (SM_AHI + W_HALF)
#define SM_BHI (SM_ALO + W_HALF)
#define SM_BLO (SM_BHI + W_HALF)
#define SMEM_BF ((size_t)(SM_BLO + W_HALF))            // 69632 bf16
#define SMEM_BYTES (SMEM_BF * 2)                       // 139264 bytes

__global__ void __launch_bounds__(256, 1)
k_mgemm(const float* __restrict__ T0, const float* __restrict__ T1,
        const float* __restrict__ T2, const float* __restrict__ T3,
        const __nv_bfloat16* __restrict__ Wc,
        float* __restrict__ C, const float* __restrict__ bias, float slope) {
    extern __shared__ __nv_bfloat16 sm[];
    int tid = threadIdx.x;
    int wid = tid >> 5, lane = tid & 31;
    int gid = lane >> 2, qid = lane & 3;
    int wm = wid & 3, wn = wid >> 2;
    int row0 = blockIdx.x * 128;

    float acc[2][8][4];
    #pragma unroll
    for (int i = 0; i < 2; i++)
        #pragma unroll
        for (int j = 0; j < 8; j++)
            #pragma unroll
            for (int q = 0; q < 4; q++) acc[i][j][q] = 0.f;

    const float* Ts[4] = {T0, T1, T2, T3};
    for (int t = 0; t < 4; t++) {
        const float* T = Ts[t];
        for (int q = tid; q < 4096; q += 256) {
            int r = q >> 5;
            int c = (q & 31) << 2;
            int gi = row0 + r;
            float4 v = make_float4(0.f, 0.f, 0.f, 0.f);
            if (gi < NN) v = *(const float4*)&T[(size_t)gi * HH + c];
            if (t == 0) {   // T0 = BN(acc): apply folded scale/shift per channel
                float4 s4 = *(const float4*)&g_bnsc[c];
                float4 h4 = *(const float4*)&g_bnsh[c];
                v.x = v.x * s4.x + h4.x; v.y = v.y * s4.y + h4.y;
                v.z = v.z * s4.z + h4.z; v.w = v.w * s4.w + h4.w;
            }
            __nv_bfloat16 hx = __float2bfloat16(v.x), hy = __float2bfloat16(v.y);
            __nv_bfloat16 hz = __float2bfloat16(v.z), hw = __float2bfloat16(v.w);
            int o = r * WK_STRIDE + c;
            sm[SM_AHI + o + 0] = hx; sm[SM_AHI + o + 1] = hy;
            sm[SM_AHI + o + 2] = hz; sm[SM_AHI + o + 3] = hw;
            sm[SM_ALO + o + 0] = __float2bfloat16(v.x - __bfloat162float(hx));
            sm[SM_ALO + o + 1] = __float2bfloat16(v.y - __bfloat162float(hy));
            sm[SM_ALO + o + 2] = __float2bfloat16(v.z - __bfloat162float(hz));
            sm[SM_ALO + o + 3] = __float2bfloat16(v.w - __bfloat162float(hw));
        }
        {
            const int4* src = (const int4*)(Wc + (size_t)t * W_TERM);
            int4* dst = (int4*)(sm + SM_BHI);
            for (int q = tid; q < (2 * W_HALF * 2) / 16; q += 256) dst[q] = src[q];
        }
        __syncthreads();

        #pragma unroll
        for (int pass = 0; pass < 3; pass++) {
            const __nv_bfloat16* Ab = sm + ((pass == 2) ? SM_ALO : SM_AHI);
            const __nv_bfloat16* Bb = sm + ((pass == 1) ? SM_BLO : SM_BHI);
            #pragma unroll
            for (int ks = 0; ks < 8; ks++) {
                int k0 = ks * 16;
                uint32_t a[2][4];
                #pragma unroll
                for (int mt = 0; mt < 2; mt++) {
                    int r = wm * 32 + mt * 16 + gid;
                    a[mt][0] = *(const uint32_t*)&Ab[(r    ) * WK_STRIDE + k0     + qid * 2];
                    a[mt][1] = *(const uint32_t*)&Ab[(r + 8) * WK_STRIDE + k0     + qid * 2];
                    a[mt][2] = *(const uint32_t*)&Ab[(r    ) * WK_STRIDE + k0 + 8 + qid * 2];
                    a[mt][3] = *(const uint32_t*)&Ab[(r + 8) * WK_STRIDE + k0 + 8 + qid * 2];
                }
                #pragma unroll
                for (int nt = 0; nt < 8; nt++) {
                    int n = wn * 64 + nt * 8 + gid;
                    uint32_t b0 = *(const uint32_t*)&Bb[n * WK_STRIDE + k0     + qid * 2];
                    uint32_t b1 = *(const uint32_t*)&Bb[n * WK_STRIDE + k0 + 8 + qid * 2];
                    mma16816(acc[0][nt], a[0], b0, b1);
                    mma16816(acc[1][nt], a[1], b0, b1);
                }
            }
        }
        __syncthreads();
    }

    // --- epilogue: bias + activation + fused BN stats ---
    float* ssum = (float*)sm;          // [0:128) sum, [128:256) sumsq
    if (bias) {
        ssum[tid] = 0.f;               // blockDim == 256
        __syncthreads();
    }
    float scol[8][2], sqcol[8][2];
    #pragma unroll
    for (int nt = 0; nt < 8; nt++) {
        scol[nt][0] = 0.f; scol[nt][1] = 0.f;
        sqcol[nt][0] = 0.f; sqcol[nt][1] = 0.f;
    }
    #pragma unroll
    for (int mt = 0; mt < 2; mt++) {
        int r0 = row0 + wm * 32 + mt * 16 + gid;
        #pragma unroll
        for (int nt = 0; nt < 8; nt++) {
            int col = wn * 64 + nt * 8 + qid * 2;
            float c0 = acc[mt][nt][0], c1 = acc[mt][nt][1];
            float c2 = acc[mt][nt][2], c3 = acc[mt][nt][3];
            if (bias) {
                float bv0 = bias[col], bv1 = bias[col + 1];
                c0 += bv0; c0 = (c0 > 0.f) ? c0 : slope * c0;
                c1 += bv1; c1 = (c1 > 0.f) ? c1 : slope * c1;
                c2 += bv0; c2 = (c2 > 0.f) ? c2 : slope * c2;
                c3 += bv1; c3 = (c3 > 0.f) ? c3 : slope * c3;
                if (r0 < NN) {
                    scol[nt][0] += c0; sqcol[nt][0] += c0 * c0;
                    scol[nt][1] += c1; sqcol[nt][1] += c1 * c1;
                }
                if (r0 + 8 < NN) {
                    scol[nt][0] += c2; sqcol[nt][0] += c2 * c2;
                    scol[nt][1] += c3; sqcol[nt][1] += c3 * c3;
                }
            }
            if (r0 < NN)     *(float2*)&C[(size_t)r0 * HH + col]       = make_float2(c0, c1);
            if (r0 + 8 < NN) *(float2*)&C[(size_t)(r0 + 8) * HH + col] = make_float2(c2, c3);
        }
    }
    if (bias) {
        #pragma unroll
        for (int nt = 0; nt < 8; nt++) {
            #pragma unroll
            for (int j = 0; j < 2; j++) {
                float s = scol[nt][j], q = sqcol[nt][j];
                #pragma unroll
                for (int off = 4; off < 32; off <<= 1) {   // reduce across gid
                    s += __shfl_xor_sync(0xFFFFFFFFu, s, off);
                    q += __shfl_xor_sync(0xFFFFFFFFu, q, off);
                }
                if (lane < 4) {
                    int col = wn * 64 + nt * 8 + qid * 2 + j;
                    atomicAdd(&ssum[col], s);
                    atomicAdd(&ssum[128 + col], q);
                }
            }
        }
        __syncthreads();
        if (tid < 128) atomicAdd(&g_sum[tid], ssum[tid]);
        else           atomicAdd(&g_sumsq[tid - 128], ssum[tid]);
    }
}

// ================= final: +b4, L2-normalize, project 128->3 =================
__global__ void k_final(const float* __restrict__ b4, const float* __restrict__ Wm,
                        const float* __restrict__ bm, float* __restrict__ out) {
    __shared__ float wm[HH * 3];
    __shared__ float bb[HH];
    __shared__ float bmv[3];
    for (int i = threadIdx.x; i < HH * 3; i += blockDim.x) wm[i] = Wm[i];
    if (threadIdx.x < HH) bb[threadIdx.x] = b4[threadIdx.x];
    if (threadIdx.x < 3) bmv[threadIdx.x] = bm[threadIdx.x];
    __syncthreads();
    int gw = (blockIdx.x * blockDim.x + threadIdx.x) >> 5;
    int lane = threadIdx.x & 31;
    if (gw >= NN) return;
    float4 v = *(const float4*)&g_acc[(size_t)gw * HH + lane * 4];
    v.x += bb[lane * 4 + 0]; v.y += bb[lane * 4 + 1];
    v.z += bb[lane * 4 + 2]; v.w += bb[lane * 4 + 3];
    float sq = v.x * v.x + v.y * v.y + v.z * v.z + v.w * v.w;
    #pragma unroll
    for (int off = 16; off; off >>= 1) sq += __shfl_xor_sync(0xFFFFFFFFu, sq, off);
    float inv = 1.0f / fmaxf(sqrtf(sq), 1e-12f);
    v.x *= inv; v.y *= inv; v.z *= inv; v.w *= inv;
    float o0 = 0.f, o1 = 0.f, o2 = 0.f;
    float vv[4] = {v.x, v.y, v.z, v.w};
    #pragma unroll
    for (int t = 0; t < 4; t++) {
        int h = lane * 4 + t;
        o0 += vv[t] * wm[h * 3 + 0];
        o1 += vv[t] * wm[h * 3 + 1];
        o2 += vv[t] * wm[h * 3 + 2];
    }
    #pragma unroll
    for (int off = 16; off; off >>= 1) {
        o0 += __shfl_xor_sync(0xFFFFFFFFu, o0, off);
        o1 += __shfl_xor_sync(0xFFFFFFFFu, o1, off);
        o2 += __shfl_xor_sync(0xFFFFFFFFu, o2, off);
    }
    if (lane == 0) {
        out[gw * 3 + 0] = o0 + bmv[0];
        out[gw * 3 + 1] = o1 + bmv[1];
        out[gw * 3 + 2] = o2 + bmv[2];
    }
}

// ================= host =================
static inline int GB(long long n, int b) { return (int)((n + b - 1) / b); }

extern "C" void kernel_launch(void* const* d_in, const int* in_sizes, int n_in,
                              void* d_out, int out_size) {
    const float* x   = (const float*)d_in[0];
    const int*   ei  = (const int*)  d_in[1];
    const float* W1  = (const float*)d_in[2];  const float* b1  = (const float*)d_in[3];
    const float* W2  = (const float*)d_in[4];  const float* b2  = (const float*)d_in[5];
    const float* W3  = (const float*)d_in[6];  const float* b3  = (const float*)d_in[7];
    const float* W4  = (const float*)d_in[8];  const float* b4  = (const float*)d_in[9];
    const float* gm1 = (const float*)d_in[10]; const float* be1 = (const float*)d_in[11];
    const float* gm2 = (const float*)d_in[12]; const float* be2 = (const float*)d_in[13];
    const float* gm3 = (const float*)d_in[14]; const float* be3 = (const float*)d_in[15];
    const float* Wm  = (const float*)d_in[16]; const float* bm  = (const float*)d_in[17];
    float* out = (float*)d_out;

    float *p_T1, *p_T2, *p_T3, *p_acc, *p_q1, *p_q2, *p_q3;
    __nv_bfloat16* p_Wc;
    cudaGetSymbolAddress((void**)&p_T1,  g_T1);
    cudaGetSymbolAddress((void**)&p_T2,  g_T2);
    cudaGetSymbolAddress((void**)&p_T3,  g_T3);
    cudaGetSymbolAddress((void**)&p_acc, g_acc);
    cudaGetSymbolAddress((void**)&p_q1,  g_q1);
    cudaGetSymbolAddress((void**)&p_q2,  g_q2);
    cudaGetSymbolAddress((void**)&p_q3,  g_q3);
    cudaGetSymbolAddress((void**)&p_Wc,  g_Wc);

    cudaFuncSetAttribute(k_mgemm, cudaFuncAttributeMaxDynamicSharedMemorySize,
                         (int)SMEM_BYTES);

    // --- graph setup ---
    k_zero   <<<GB(NN, 256), 256>>>();
    k_degree <<<GB(EE, 256), 256>>>(ei);
    k_dinv   <<<GB(NN, 256), 256>>>();
    k_bsum   <<<NSCB, SCB>>>();
    k_bscan  <<<1, 1>>>();
    k_scanfin<<<NSCB, SCB>>>();
    k_scatter<<<GB(EE, 256), 256>>>(ei);
    k_wconv  <<<GB(4 * 16384, 256), 256>>>(W2, p_Wc);
    k_wconv  <<<GB(4 * 16384, 256), 256>>>(W3, p_Wc + W_LAYER);
    k_wconv  <<<GB(4 * 16384, 256), 256>>>(W4, p_Wc + 2 * W_LAYER);

    // --- layer 1 (3 -> 128), leaky_relu; stats fused; BN folded into sc/sh ---
    k_prop3<<<GB(NN, 256), 256>>>(x,    x,    p_q1, 1.f,  0.f);
    k_prop3<<<GB(NN, 256), 256>>>(p_q1, x,    p_q2, 2.f, -1.f);
    k_prop3<<<GB(NN, 256), 256>>>(p_q2, p_q1, p_q3, 2.f, -1.f);
    k_layer1<<<GB(NN, L1_ROWS), 128>>>(x, W1, b1);
    k_bnfin<<<1, 128>>>(gm1, be1);

    const int propBlocks = GB((long long)NN * 32, 256);
    const int gemmBlocks = GB(NN, 128);

    // --- layer 2 (128 -> 128), leaky_relu + BN ---
    k_prop128<<<propBlocks, 256>>>(p_acc, p_acc, p_T1, 1.f,  0.f, 1, 0);
    k_prop128<<<propBlocks, 256>>>(p_T1,  p_acc, p_T2, 2.f, -1.f, 0, 1);
    k_prop128<<<propBlocks, 256>>>(p_T2,  p_T1,  p_T3, 2.f, -1.f, 0, 0);
    k_mgemm<<<gemmBlocks, 256, SMEM_BYTES>>>(p_acc, p_T1, p_T2, p_T3, p_Wc, p_acc, b2, 0.01f);
    k_bnfin<<<1, 128>>>(gm2, be2);

    // --- layer 3 (128 -> 128), relu + BN ---
    k_prop128<<<propBlocks, 256>>>(p_acc, p_acc, p_T1, 1.f,  0.f, 1, 0);
    k_prop128<<<propBlocks, 256>>>(p_T1,  p_acc, p_T2, 2.f, -1.f, 0, 1);
    k_prop128<<<propBlocks, 256>>>(p_T2,  p_T1,  p_T3, 2.f, -1.f, 0, 0);
    k_mgemm<<<gemmBlocks, 256, SMEM_BYTES>>>(p_acc, p_T1, p_T2, p_T3, p_Wc + W_LAYER, p_acc, b3, 0.0f);
    k_bnfin<<<1, 128>>>(gm3, be3);

    // --- layer 4 (128 -> 128), then normalize + project ---
    k_prop128<<<propBlocks, 256>>>(p_acc, p_acc, p_T1, 1.f,  0.f, 1, 0);
    k_prop128<<<propBlocks, 256>>>(p_T1,  p_acc, p_T2, 2.f, -1.f, 0, 1);
    k_prop128<<<propBlocks, 256>>>(p_T2,  p_T1,  p_T3, 2.f, -1.f, 0, 0);
    k_mgemm<<<gemmBlocks, 256, SMEM_BYTES>>>(p_acc, p_T1, p_T2, p_T3, p_Wc + 2 * W_LAYER, p_acc,
                                             (const float*)nullptr, 0.0f);
    k_final<<<GB((long long)NN * 32, 256), 256>>>(b4, Wm, bm, out);
}

// round 13
// speedup vs baseline: 1.1135x; 1.0163x over previous
#include <cuda_runtime.h>
#include <cuda_bf16.h>
#include <math.h>
#include <stdint.h>

#define NN 50000
#define EE 800000
#define HH 128

// ================= scratch (static device globals; no allocation) =================
__device__ float g_deg[NN];
__device__ int   g_indeg[NN];
__device__ int   g_rowptr[NN + 1];
__device__ int   g_cursor[NN];
__device__ int2  g_colw[EE];              // packed {src, wgt-as-int}

__device__ float g_T1 [(size_t)NN * HH];
__device__ float g_T2 [(size_t)NN * HH];
__device__ float g_T3 [(size_t)NN * HH];
__device__ float g_acc[(size_t)NN * HH];

__device__ float g_q1[NN * 3], g_q2[NN * 3], g_q3[NN * 3];
__device__ float g_sum[HH], g_sumsq[HH];
__device__ float g_bnsc[HH], g_bnsh[HH];   // folded BN: h = sc*acc + sh
__device__ float g_W1t[4 * 3 * HH];        // monomial-transformed layer-1 weights

// pre-converted bf16 hi/lo weights (monomial basis), padded [n][k] layout:
#define WK_STRIDE 136
#define W_HALF    (HH * WK_STRIDE)            // 17408 bf16
#define W_TERM    (2 * W_HALF)                // 34816 bf16
#define W_LAYER   (4 * W_TERM)                // 139264 bf16
__device__ __nv_bfloat16 g_Wc[3 * W_LAYER];

#define SCB 512
#define NSCB ((NN + SCB - 1) / SCB)
__device__ int g_bsum[NSCB];

// ================= mma.sync + cp.async helpers (sm_80 baseline) ==================
__device__ __forceinline__ void mma16816(float* c, const uint32_t* a,
                                         uint32_t b0, uint32_t b1) {
    asm volatile(
        "mma.sync.aligned.m16n8k16.row.col.f32.bf16.bf16.f32 "
        "{%0,%1,%2,%3}, {%4,%5,%6,%7}, {%8,%9}, {%0,%1,%2,%3};\n"
        : "+f"(c[0]), "+f"(c[1]), "+f"(c[2]), "+f"(c[3])
        : "r"(a[0]), "r"(a[1]), "r"(a[2]), "r"(a[3]), "r"(b0), "r"(b1));
}
__device__ __forceinline__ uint32_t smem_u32(const void* p) {
    uint32_t a;
    asm("{ .reg .u64 t; cvta.to.shared.u64 t, %1; cvt.u32.u64 %0, t; }" : "=r"(a) : "l"(p));
    return a;
}
__device__ __forceinline__ void cp_async16(uint32_t dst, const void* src) {
    asm volatile("cp.async.ca.shared.global [%0], [%1], 16;" :: "r"(dst), "l"(src));
}
#define CP_COMMIT() asm volatile("cp.async.commit_group;" ::: "memory")
#define CP_WAIT(N)  asm volatile("cp.async.wait_group %0;" :: "n"(N) : "memory")

// ================= setup kernels =================
__global__ void k_zero() {
    int i = blockIdx.x * blockDim.x + threadIdx.x;
    if (i < NN) { g_deg[i] = 0.f; g_indeg[i] = 0; }
    if (i < HH) { g_sum[i] = 0.f; g_sumsq[i] = 0.f; }
}

__global__ void k_degree(const int* __restrict__ ei) {
    int e = blockIdx.x * blockDim.x + threadIdx.x;
    if (e >= EE) return;
    atomicAdd(&g_deg[ei[e]], 1.0f);
    atomicAdd(&g_indeg[ei[EE + e]], 1);
}

__global__ void k_dinv() {
    int i = blockIdx.x * blockDim.x + threadIdx.x;
    if (i >= NN) return;
    float d = g_deg[i];
    g_deg[i] = (d > 0.f) ? rsqrtf(d) : 0.f;
}

// ---- block-parallel exclusive scan of indeg -> rowptr ----
__global__ void k_bsum() {
    __shared__ int sh[SCB];
    int i = blockIdx.x * SCB + threadIdx.x;
    sh[threadIdx.x] = (i < NN) ? g_indeg[i] : 0;
    __syncthreads();
    for (int off = SCB / 2; off > 0; off >>= 1) {
        if (threadIdx.x < off) sh[threadIdx.x] += sh[threadIdx.x + off];
        __syncthreads();
    }
    if (threadIdx.x == 0) g_bsum[blockIdx.x] = sh[0];
}
__global__ void k_bscan() {
    int acc = 0;
    for (int i = 0; i < NSCB; i++) { int v = g_bsum[i]; g_bsum[i] = acc; acc += v; }
    g_rowptr[NN] = acc;
}
__global__ void k_scanfin() {
    __shared__ int sh[SCB];
    int t = threadIdx.x;
    int i = blockIdx.x * SCB + t;
    int v = (i < NN) ? g_indeg[i] : 0;
    sh[t] = v;
    __syncthreads();
    for (int off = 1; off < SCB; off <<= 1) {
        int add = (t >= off) ? sh[t - off] : 0;
        __syncthreads();
        sh[t] += add;
        __syncthreads();
    }
    if (i < NN) {
        int ex = g_bsum[blockIdx.x] + sh[t] - v;
        g_rowptr[i] = ex;
        g_cursor[i] = ex;
    }
}

__global__ void k_scatter(const int* __restrict__ ei) {
    int e = blockIdx.x * blockDim.x + threadIdx.x;
    if (e >= EE) return;
    int s = ei[e];
    int d = ei[EE + e];
    float w = -g_deg[s] * g_deg[d];
    int pos = atomicAdd(&g_cursor[d], 1);
    g_colw[pos] = make_int2(s, __float_as_int(w));
}

// ---- W conversion + Chebyshev->monomial transform:
//      W~0 = W0 - W2, W~1 = W1 - 3W3, W~2 = 2W2, W~3 = 4W3
//      fp32 [4][128k][128n] -> bf16 hi/lo [t][n][k] (stride 136) ----
__global__ void k_wconv(const float* __restrict__ W, __nv_bfloat16* __restrict__ dst) {
    int idx = blockIdx.x * blockDim.x + threadIdx.x;
    if (idx >= 16384) return;
    int n = idx >> 7;
    int k = idx & 127;
    int base = (k << 7) + n;
    float w0 = W[base];
    float w1 = W[base + 16384];
    float w2 = W[base + 32768];
    float w3 = W[base + 49152];
    float wt[4];
    wt[0] = w0 - w2;
    wt[1] = w1 - 3.0f * w3;
    wt[2] = 2.0f * w2;
    wt[3] = 4.0f * w3;
    #pragma unroll
    for (int t = 0; t < 4; t++) {
        __nv_bfloat16 hi = __float2bfloat16(wt[t]);
        __nv_bfloat16 lo = __float2bfloat16(wt[t] - __bfloat162float(hi));
        __nv_bfloat16* p = dst + (size_t)t * W_TERM + n * WK_STRIDE + k;
        p[0] = hi;
        p[W_HALF] = lo;
    }
}

// layer-1 weights [4][3][128] -> monomial fp32
__global__ void k_wconv1(const float* __restrict__ W) {
    int idx = threadIdx.x + blockIdx.x * blockDim.x;   // 384
    if (idx >= 384) return;
    float w0 = W[idx], w1 = W[idx + 384], w2 = W[idx + 768], w3 = W[idx + 1152];
    g_W1t[idx]        = w0 - w2;
    g_W1t[idx + 384]  = w1 - 3.0f * w3;
    g_W1t[idx + 768]  = 2.0f * w2;
    g_W1t[idx + 1152] = 4.0f * w3;
}

// ================= propagation: out = L @ t (pure), optional BN fold on src ======
__global__ void k_prop128(const float* __restrict__ t, float* __restrict__ out,
                          int bn_src) {
    int gw = (blockIdx.x * blockDim.x + threadIdx.x) >> 5;
    int lane = threadIdx.x & 31;
    if (gw >= NN) return;
    float4 sc, sh;
    if (bn_src) {
        sc = *(const float4*)&g_bnsc[lane * 4];
        sh = *(const float4*)&g_bnsh[lane * 4];
    }
    int beg = g_rowptr[gw], end = g_rowptr[gw + 1];
    float ax = 0.f, ay = 0.f, az = 0.f, aw = 0.f, ws = 0.f;
    for (int e = beg; e < end; e++) {
        int2 cw = __ldg(&g_colw[e]);
        float w = __int_as_float(cw.y);
        float4 v = *(const float4*)&t[(size_t)cw.x * HH + lane * 4];
        ax += w * v.x; ay += w * v.y; az += w * v.z; aw += w * v.w;
        ws += w;
    }
    float4 r;
    if (bn_src) {
        r.x = sc.x * ax + sh.x * ws;
        r.y = sc.y * ay + sh.y * ws;
        r.z = sc.z * az + sh.z * ws;
        r.w = sc.w * aw + sh.w * ws;
    } else {
        r.x = ax; r.y = ay; r.z = az; r.w = aw;
    }
    *(float4*)&out[(size_t)gw * HH + lane * 4] = r;
}

__global__ void k_prop3(const float* __restrict__ t, float* __restrict__ out) {
    int i = blockIdx.x * blockDim.x + threadIdx.x;
    if (i >= NN) return;
    int beg = g_rowptr[i], end = g_rowptr[i + 1];
    float a0 = 0.f, a1 = 0.f, a2 = 0.f;
    for (int e = beg; e < end; e++) {
        int2 cw = g_colw[e];
        float w = __int_as_float(cw.y);
        a0 += w * t[cw.x * 3 + 0];
        a1 += w * t[cw.x * 3 + 1];
        a2 += w * t[cw.x * 3 + 2];
    }
    out[i * 3 + 0] = a0;
    out[i * 3 + 1] = a1;
    out[i * 3 + 2] = a2;
}

// ================= layer 1 (3->128) SIMT, monomial weights, stats fused ==========
#define L1_ROWS 64
__global__ void k_layer1(const float* __restrict__ x, const float* __restrict__ b1) {
    __shared__ float w[4 * 3 * HH];
    __shared__ float bb[HH];
    for (int i = threadIdx.x; i < 4 * 3 * HH; i += blockDim.x) w[i] = g_W1t[i];
    if (threadIdx.x < HH) bb[threadIdx.x] = b1[threadIdx.x];
    __syncthreads();
    int h = threadIdx.x;
    int row0 = blockIdx.x * L1_ROWS;
    float s = 0.f, sq = 0.f;
    for (int r = 0; r < L1_ROWS; r++) {
        int i = row0 + r;
        if (i >= NN) break;
        float acc = bb[h];
        #pragma unroll
        for (int c = 0; c < 3; c++) {
            acc += x[i * 3 + c]    * w[(0 * 3 + c) * HH + h];
            acc += g_q1[i * 3 + c] * w[(1 * 3 + c) * HH + h];
            acc += g_q2[i * 3 + c] * w[(2 * 3 + c) * HH + h];
            acc += g_q3[i * 3 + c] * w[(3 * 3 + c) * HH + h];
        }
        float y = (acc > 0.f) ? acc : 0.01f * acc;
        g_acc[(size_t)i * HH + h] = y;
        s += y; sq += y * y;
    }
    atomicAdd(&g_sum[h], s);
    atomicAdd(&g_sumsq[h], sq);
}

// ================= BN finalize: fold (m, rstd, gamma, beta) -> sc/sh =============
__global__ void k_bnfin(const float* __restrict__ gam, const float* __restrict__ bet) {
    int h = threadIdx.x;
    float m = g_sum[h] * (1.0f / NN);
    float v = g_sumsq[h] * (1.0f / NN) - m * m;
    float r = rsqrtf(v + 1e-5f);
    float sc = gam[h] * r;
    g_bnsc[h] = sc;
    g_bnsh[h] = bet[h] - m * sc;
    g_sum[h] = 0.f;
    g_sumsq[h] = 0.f;
}

// ================= mma.sync split-bf16 4-term GEMM, cp.async B double-buffer =====
// C = act( BN(T0)@W~0 + T1@W~1 + T2@W~2 + T3@W~3 + bias ), stats fused if bias.
#define SM_AHI 0
#define SM_ALO (SM_AHI + W_HALF)
#define SM_B0  (SM_ALO + W_HALF)              // two 34816-bf16 B buffers
#define SM_B1  (SM_B0 + W_TERM)
#define SMEM_BF ((size_t)(SM_B1 + W_TERM))    // 104448 bf16
#define SMEM_BYTES (SMEM_BF * 2)              // 208896 bytes

__global__ void __launch_bounds__(256, 1)
k_mgemm(const float* __restrict__ T0, const float* __restrict__ T1,
        const float* __restrict__ T2, const float* __restrict__ T3,
        const __nv_bfloat16* __restrict__ Wc,
        float* __restrict__ C, const float* __restrict__ bias, float slope) {
    extern __shared__ __nv_bfloat16 sm[];
    int tid = threadIdx.x;
    int wid = tid >> 5, lane = tid & 31;
    int gid = lane >> 2, qid = lane & 3;
    int wm = wid & 3, wn = wid >> 2;
    int row0 = blockIdx.x * 128;
    uint32_t sb = smem_u32(sm);

    float acc[2][8][4];
    #pragma unroll
    for (int i = 0; i < 2; i++)
        #pragma unroll
        for (int j = 0; j < 8; j++)
            #pragma unroll
            for (int q = 0; q < 4; q++) acc[i][j][q] = 0.f;

    // prefetch B(0)
    {
        const char* src = (const char*)(Wc);
        uint32_t dst = sb + SM_B0 * 2;
        for (int q = tid; q < 4352; q += 256)
            cp_async16(dst + q * 16, src + q * 16);
        CP_COMMIT();
    }

    const float* Ts[4] = {T0, T1, T2, T3};
    for (int t = 0; t < 4; t++) {
        // --- stage A(t): fp32 -> bf16 hi/lo (BN fold on t==0) ---
        const float* T = Ts[t];
        for (int q = tid; q < 4096; q += 256) {
            int r = q >> 5;
            int c = (q & 31) << 2;
            int gi = row0 + r;
            float4 v = make_float4(0.f, 0.f, 0.f, 0.f);
            if (gi < NN) v = *(const float4*)&T[(size_t)gi * HH + c];
            if (t == 0) {
                float4 s4 = *(const float4*)&g_bnsc[c];
                float4 h4 = *(const float4*)&g_bnsh[c];
                v.x = v.x * s4.x + h4.x; v.y = v.y * s4.y + h4.y;
                v.z = v.z * s4.z + h4.z; v.w = v.w * s4.w + h4.w;
            }
            __nv_bfloat16 hx = __float2bfloat16(v.x), hy = __float2bfloat16(v.y);
            __nv_bfloat16 hz = __float2bfloat16(v.z), hw = __float2bfloat16(v.w);
            int o = r * WK_STRIDE + c;
            sm[SM_AHI + o + 0] = hx; sm[SM_AHI + o + 1] = hy;
            sm[SM_AHI + o + 2] = hz; sm[SM_AHI + o + 3] = hw;
            sm[SM_ALO + o + 0] = __float2bfloat16(v.x - __bfloat162float(hx));
            sm[SM_ALO + o + 1] = __float2bfloat16(v.y - __bfloat162float(hy));
            sm[SM_ALO + o + 2] = __float2bfloat16(v.z - __bfloat162float(hz));
            sm[SM_ALO + o + 3] = __float2bfloat16(v.w - __bfloat162float(hw));
        }
        // --- prefetch B(t+1) into alternate buffer ---
        if (t < 3) {
            const char* src = (const char*)(Wc + (size_t)(t + 1) * W_TERM);
            uint32_t dst = sb + (((t + 1) & 1) ? SM_B1 : SM_B0) * 2;
            for (int q = tid; q < 4352; q += 256)
                cp_async16(dst + q * 16, src + q * 16);
            CP_COMMIT();
            CP_WAIT(1);     // B(t) complete
        } else {
            CP_WAIT(0);
        }
        __syncthreads();

        const __nv_bfloat16* Bbuf = sm + ((t & 1) ? SM_B1 : SM_B0);
        #pragma unroll
        for (int pass = 0; pass < 3; pass++) {
            const __nv_bfloat16* Ab = sm + ((pass == 2) ? SM_ALO : SM_AHI);
            const __nv_bfloat16* Bb = Bbuf + ((pass == 1) ? W_HALF : 0);
            #pragma unroll
            for (int ks = 0; ks < 8; ks++) {
                int k0 = ks * 16;
                uint32_t a[2][4];
                #pragma unroll
                for (int mt = 0; mt < 2; mt++) {
                    int r = wm * 32 + mt * 16 + gid;
                    a[mt][0] = *(const uint32_t*)&Ab[(r    ) * WK_STRIDE + k0     + qid * 2];
                    a[mt][1] = *(const uint32_t*)&Ab[(r + 8) * WK_STRIDE + k0     + qid * 2];
                    a[mt][2] = *(const uint32_t*)&Ab[(r    ) * WK_STRIDE + k0 + 8 + qid * 2];
                    a[mt][3] = *(const uint32_t*)&Ab[(r + 8) * WK_STRIDE + k0 + 8 + qid * 2];
                }
                #pragma unroll
                for (int nt = 0; nt < 8; nt++) {
                    int n = wn * 64 + nt * 8 + gid;
                    uint32_t b0 = *(const uint32_t*)&Bb[n * WK_STRIDE + k0     + qid * 2];
                    uint32_t b1 = *(const uint32_t*)&Bb[n * WK_STRIDE + k0 + 8 + qid * 2];
                    mma16816(acc[0][nt], a[0], b0, b1);
                    mma16816(acc[1][nt], a[1], b0, b1);
                }
            }
        }
        __syncthreads();
    }

    // --- epilogue: bias + activation + fused BN stats ---
    float* ssum = (float*)sm;          // [0:128) sum, [128:256) sumsq
    if (bias) {
        ssum[tid] = 0.f;
        __syncthreads();
    }
    float scol[8][2], sqcol[8][2];
    #pragma unroll
    for (int nt = 0; nt < 8; nt++) {
        scol[nt][0] = 0.f; scol[nt][1] = 0.f;
        sqcol[nt][0] = 0.f; sqcol[nt][1] = 0.f;
    }
    #pragma unroll
    for (int mt = 0; mt < 2; mt++) {
        int r0 = row0 + wm * 32 + mt * 16 + gid;
        #pragma unroll
        for (int nt = 0; nt < 8; nt++) {
            int col = wn * 64 + nt * 8 + qid * 2;
            float c0 = acc[mt][nt][0], c1 = acc[mt][nt][1];
            float c2 = acc[mt][nt][2], c3 = acc[mt][nt][3];
            if (bias) {
                float bv0 = bias[col], bv1 = bias[col + 1];
                c0 += bv0; c0 = (c0 > 0.f) ? c0 : slope * c0;
                c1 += bv1; c1 = (c1 > 0.f) ? c1 : slope * c1;
                c2 += bv0; c2 = (c2 > 0.f) ? c2 : slope * c2;
                c3 += bv1; c3 = (c3 > 0.f) ? c3 : slope * c3;
                if (r0 < NN) {
                    scol[nt][0] += c0; sqcol[nt][0] += c0 * c0;
                    scol[nt][1] += c1; sqcol[nt][1] += c1 * c1;
                }
                if (r0 + 8 < NN) {
                    scol[nt][0] += c2; sqcol[nt][0] += c2 * c2;
                    scol[nt][1] += c3; sqcol[nt][1] += c3 * c3;
                }
            }
            if (r0 < NN)     *(float2*)&C[(size_t)r0 * HH + col]       = make_float2(c0, c1);
            if (r0 + 8 < NN) *(float2*)&C[(size_t)(r0 + 8) * HH + col] = make_float2(c2, c3);
        }
    }
    if (bias) {
        #pragma unroll
        for (int nt = 0; nt < 8; nt++) {
            #pragma unroll
            for (int j = 0; j < 2; j++) {
                float s = scol[nt][j], q = sqcol[nt][j];
                #pragma unroll
                for (int off = 4; off < 32; off <<= 1) {
                    s += __shfl_xor_sync(0xFFFFFFFFu, s, off);
                    q += __shfl_xor_sync(0xFFFFFFFFu, q, off);
                }
                if (lane < 4) {
                    int col = wn * 64 + nt * 8 + qid * 2 + j;
                    atomicAdd(&ssum[col], s);
                    atomicAdd(&ssum[128 + col], q);
                }
            }
        }
        __syncthreads();
        if (tid < 128) atomicAdd(&g_sum[tid], ssum[tid]);
        else           atomicAdd(&g_sumsq[tid - 128], ssum[tid]);
    }
}

// ================= final: +b4, L2-normalize, project 128->3 =================
__global__ void k_final(const float* __restrict__ b4, const float* __restrict__ Wm,
                        const float* __restrict__ bm, float* __restrict__ out) {
    __shared__ float wm[HH * 3];
    __shared__ float bb[HH];
    __shared__ float bmv[3];
    for (int i = threadIdx.x; i < HH * 3; i += blockDim.x) wm[i] = Wm[i];
    if (threadIdx.x < HH) bb[threadIdx.x] = b4[threadIdx.x];
    if (threadIdx.x < 3) bmv[threadIdx.x] = bm[threadIdx.x];
    __syncthreads();
    int gw = (blockIdx.x * blockDim.x + threadIdx.x) >> 5;
    int lane = threadIdx.x & 31;
    if (gw >= NN) return;
    float4 v = *(const float4*)&g_acc[(size_t)gw * HH + lane * 4];
    v.x += bb[lane * 4 + 0]; v.y += bb[lane * 4 + 1];
    v.z += bb[lane * 4 + 2]; v.w += bb[lane * 4 + 3];
    float sq = v.x * v.x + v.y * v.y + v.z * v.z + v.w * v.w;
    #pragma unroll
    for (int off = 16; off; off >>= 1) sq += __shfl_xor_sync(0xFFFFFFFFu, sq, off);
    float inv = 1.0f / fmaxf(sqrtf(sq), 1e-12f);
    v.x *= inv; v.y *= inv; v.z *= inv; v.w *= inv;
    float o0 = 0.f, o1 = 0.f, o2 = 0.f;
    float vv[4] = {v.x, v.y, v.z, v.w};
    #pragma unroll
    for (int t = 0; t < 4; t++) {
        int h = lane * 4 + t;
        o0 += vv[t] * wm[h * 3 + 0];
        o1 += vv[t] * wm[h * 3 + 1];
        o2 += vv[t] * wm[h * 3 + 2];
    }
    #pragma unroll
    for (int off = 16; off; off >>= 1) {
        o0 += __shfl_xor_sync(0xFFFFFFFFu, o0, off);
        o1 += __shfl_xor_sync(0xFFFFFFFFu, o1, off);
        o2 += __shfl_xor_sync(0xFFFFFFFFu, o2, off);
    }
    if (lane == 0) {
        out[gw * 3 + 0] = o0 + bmv[0];
        out[gw * 3 + 1] = o1 + bmv[1];
        out[gw * 3 + 2] = o2 + bmv[2];
    }
}

// ================= host =================
static inline int GB(long long n, int b) { return (int)((n + b - 1) / b); }

extern "C" void kernel_launch(void* const* d_in, const int* in_sizes, int n_in,
                              void* d_out, int out_size) {
    const float* x   = (const float*)d_in[0];
    const int*   ei  = (const int*)  d_in[1];
    const float* W1  = (const float*)d_in[2];  const float* b1  = (const float*)d_in[3];
    const float* W2  = (const float*)d_in[4];  const float* b2  = (const float*)d_in[5];
    const float* W3  = (const float*)d_in[6];  const float* b3  = (const float*)d_in[7];
    const float* W4  = (const float*)d_in[8];  const float* b4  = (const float*)d_in[9];
    const float* gm1 = (const float*)d_in[10]; const float* be1 = (const float*)d_in[11];
    const float* gm2 = (const float*)d_in[12]; const float* be2 = (const float*)d_in[13];
    const float* gm3 = (const float*)d_in[14]; const float* be3 = (const float*)d_in[15];
    const float* Wm  = (const float*)d_in[16]; const float* bm  = (const float*)d_in[17];
    float* out = (float*)d_out;

    float *p_T1, *p_T2, *p_T3, *p_acc, *p_q1, *p_q2, *p_q3;
    __nv_bfloat16* p_Wc;
    cudaGetSymbolAddress((void**)&p_T1,  g_T1);
    cudaGetSymbolAddress((void**)&p_T2,  g_T2);
    cudaGetSymbolAddress((void**)&p_T3,  g_T3);
    cudaGetSymbolAddress((void**)&p_acc, g_acc);
    cudaGetSymbolAddress((void**)&p_q1,  g_q1);
    cudaGetSymbolAddress((void**)&p_q2,  g_q2);
    cudaGetSymbolAddress((void**)&p_q3,  g_q3);
    cudaGetSymbolAddress((void**)&p_Wc,  g_Wc);

    cudaFuncSetAttribute(k_mgemm, cudaFuncAttributeMaxDynamicSharedMemorySize,
                         (int)SMEM_BYTES);

    // --- graph setup + weight transforms ---
    k_zero   <<<GB(NN, 256), 256>>>();
    k_degree <<<GB(EE, 256), 256>>>(ei);
    k_dinv   <<<GB(NN, 256), 256>>>();
    k_bsum   <<<NSCB, SCB>>>();
    k_bscan  <<<1, 1>>>();
    k_scanfin<<<NSCB, SCB>>>();
    k_scatter<<<GB(EE, 256), 256>>>(ei);
    k_wconv  <<<GB(16384, 256), 256>>>(W2, p_Wc);
    k_wconv  <<<GB(16384, 256), 256>>>(W3, p_Wc + W_LAYER);
    k_wconv  <<<GB(16384, 256), 256>>>(W4, p_Wc + 2 * W_LAYER);
    k_wconv1 <<<2, 192>>>(W1);

    // --- layer 1 (3 -> 128): monomial basis L^k x, leaky_relu, fused stats ---
    k_prop3<<<GB(NN, 256), 256>>>(x,    p_q1);
    k_prop3<<<GB(NN, 256), 256>>>(p_q1, p_q2);
    k_prop3<<<GB(NN, 256), 256>>>(p_q2, p_q3);
    k_layer1<<<GB(NN, L1_ROWS), 128>>>(x, b1);
    k_bnfin<<<1, 128>>>(gm1, be1);

    const int propBlocks = GB((long long)NN * 32, 256);
    const int gemmBlocks = GB(NN, 128);

    // --- layer 2 (128 -> 128), leaky_relu + BN ---
    k_prop128<<<propBlocks, 256>>>(p_acc, p_T1, 1);
    k_prop128<<<propBlocks, 256>>>(p_T1,  p_T2, 0);
    k_prop128<<<propBlocks, 256>>>(p_T2,  p_T3, 0);
    k_mgemm<<<gemmBlocks, 256, SMEM_BYTES>>>(p_acc, p_T1, p_T2, p_T3, p_Wc, p_acc, b2, 0.01f);
    k_bnfin<<<1, 128>>>(gm2, be2);

    // --- layer 3 (128 -> 128), relu + BN ---
    k_prop128<<<propBlocks, 256>>>(p_acc, p_T1, 1);
    k_prop128<<<propBlocks, 256>>>(p_T1,  p_T2, 0);
    k_prop128<<<propBlocks, 256>>>(p_T2,  p_T3, 0);
    k_mgemm<<<gemmBlocks, 256, SMEM_BYTES>>>(p_acc, p_T1, p_T2, p_T3, p_Wc + W_LAYER, p_acc, b3, 0.0f);
    k_bnfin<<<1, 128>>>(gm3, be3);

    // --- layer 4 (128 -> 128), then normalize + project ---
    k_prop128<<<propBlocks, 256>>>(p_acc, p_T1, 1);
    k_prop128<<<propBlocks, 256>>>(p_T1,  p_T2, 0);
    k_prop128<<<propBlocks, 256>>>(p_T2,  p_T3, 0);
    k_mgemm<<<gemmBlocks, 256, SMEM_BYTES>>>(p_acc, p_T1, p_T2, p_T3, p_Wc + 2 * W_LAYER, p_acc,
                                             (const float*)nullptr, 0.0f);
    k_final<<<GB((long long)NN * 32, 256), 256>>>(b4, Wm, bm, out);
}

// round 15
// speedup vs baseline: 1.4436x; 1.2965x over previous
#include <cuda_runtime.h>
#include <cuda_bf16.h>
#include <cuda_fp16.h>
#include <math.h>
#include <stdint.h>

#define NN 50000
#define EE 800000
#define HH 128

// ================= scratch (static device globals; no allocation) =================
__device__ float g_deg[NN];
__device__ int   g_indeg[NN];
__device__ int   g_rowptr[NN + 1];
__device__ int   g_cursor[NN];
__device__ int2  g_colw[EE];              // packed {src, wgt-as-int}

__device__ __half g_T1h[(size_t)NN * HH];  // fp16 basis tensors
__device__ __half g_T2h[(size_t)NN * HH];
__device__ __half g_T3h[(size_t)NN * HH];
__device__ float  g_acc[(size_t)NN * HH];  // fp32 layer output (pre-BN)

__device__ float g_q1[NN * 3], g_q2[NN * 3], g_q3[NN * 3];
__device__ float g_sum[HH], g_sumsq[HH];
__device__ float g_bnsc[HH], g_bnsh[HH];   // folded BN: h = sc*acc + sh
__device__ float g_W1t[4 * 3 * HH];        // monomial-transformed layer-1 weights

// pre-converted bf16 hi/lo weights (monomial basis), padded [n][k] layout:
#define WK_STRIDE 136
#define W_HALF    (HH * WK_STRIDE)            // 17408 bf16
#define W_TERM    (2 * W_HALF)                // 34816 bf16
#define W_LAYER   (4 * W_TERM)                // 139264 bf16
__device__ __nv_bfloat16 g_Wc[3 * W_LAYER];

#define SCB 512
#define NSCB ((NN + SCB - 1) / SCB)
__device__ int g_bsum[NSCB];

// ================= mma.sync + cp.async helpers (sm_80 baseline) ==================
__device__ __forceinline__ void mma16816(float* c, const uint32_t* a,
                                         uint32_t b0, uint32_t b1) {
    asm volatile(
        "mma.sync.aligned.m16n8k16.row.col.f32.bf16.bf16.f32 "
        "{%0,%1,%2,%3}, {%4,%5,%6,%7}, {%8,%9}, {%0,%1,%2,%3};\n"
        : "+f"(c[0]), "+f"(c[1]), "+f"(c[2]), "+f"(c[3])
        : "r"(a[0]), "r"(a[1]), "r"(a[2]), "r"(a[3]), "r"(b0), "r"(b1));
}
__device__ __forceinline__ uint32_t smem_u32(const void* p) {
    uint32_t a;
    asm("{ .reg .u64 t; cvta.to.shared.u64 t, %1; cvt.u32.u64 %0, t; }" : "=r"(a) : "l"(p));
    return a;
}
__device__ __forceinline__ void cp_async16(uint32_t dst, const void* src) {
    asm volatile("cp.async.ca.shared.global [%0], [%1], 16;" :: "r"(dst), "l"(src));
}
#define CP_COMMIT() asm volatile("cp.async.commit_group;" ::: "memory")
#define CP_WAIT(N)  asm volatile("cp.async.wait_group %0;" :: "n"(N) : "memory")

// ================= setup kernels =================
__global__ void k_zero() {
    int i = blockIdx.x * blockDim.x + threadIdx.x;
    if (i < NN) { g_deg[i] = 0.f; g_indeg[i] = 0; }
    if (i < HH) { g_sum[i] = 0.f; g_sumsq[i] = 0.f; }
}

__global__ void k_degree(const int* __restrict__ ei) {
    int e = blockIdx.x * blockDim.x + threadIdx.x;
    if (e >= EE) return;
    atomicAdd(&g_deg[ei[e]], 1.0f);
    atomicAdd(&g_indeg[ei[EE + e]], 1);
}

__global__ void k_dinv() {
    int i = blockIdx.x * blockDim.x + threadIdx.x;
    if (i >= NN) return;
    float d = g_deg[i];
    g_deg[i] = (d > 0.f) ? rsqrtf(d) : 0.f;
}

// ---- block-parallel exclusive scan of indeg -> rowptr ----
__global__ void k_bsum() {
    __shared__ int sh[SCB];
    int i = blockIdx.x * SCB + threadIdx.x;
    sh[threadIdx.x] = (i < NN) ? g_indeg[i] : 0;
    __syncthreads();
    for (int off = SCB / 2; off > 0; off >>= 1) {
        if (threadIdx.x < off) sh[threadIdx.x] += sh[threadIdx.x + off];
        __syncthreads();
    }
    if (threadIdx.x == 0) g_bsum[blockIdx.x] = sh[0];
}
__global__ void k_bscan() {
    int acc = 0;
    for (int i = 0; i < NSCB; i++) { int v = g_bsum[i]; g_bsum[i] = acc; acc += v; }
    g_rowptr[NN] = acc;
}
__global__ void k_scanfin() {
    __shared__ int sh[SCB];
    int t = threadIdx.x;
    int i = blockIdx.x * SCB + t;
    int v = (i < NN) ? g_indeg[i] : 0;
    sh[t] = v;
    __syncthreads();
    for (int off = 1; off < SCB; off <<= 1) {
        int add = (t >= off) ? sh[t - off] : 0;
        __syncthreads();
        sh[t] += add;
        __syncthreads();
    }
    if (i < NN) {
        int ex = g_bsum[blockIdx.x] + sh[t] - v;
        g_rowptr[i] = ex;
        g_cursor[i] = ex;
    }
}

__global__ void k_scatter(const int* __restrict__ ei) {
    int e = blockIdx.x * blockDim.x + threadIdx.x;
    if (e >= EE) return;
    int s = ei[e];
    int d = ei[EE + e];
    float w = -g_deg[s] * g_deg[d];
    int pos = atomicAdd(&g_cursor[d], 1);
    g_colw[pos] = make_int2(s, __float_as_int(w));
}

// ---- W conversion + Chebyshev->monomial transform ----
__global__ void k_wconv(const float* __restrict__ W, __nv_bfloat16* __restrict__ dst) {
    int idx = blockIdx.x * blockDim.x + threadIdx.x;
    if (idx >= 16384) return;
    int n = idx >> 7;
    int k = idx & 127;
    int base = (k << 7) + n;
    float w0 = W[base];
    float w1 = W[base + 16384];
    float w2 = W[base + 32768];
    float w3 = W[base + 49152];
    float wt[4];
    wt[0] = w0 - w2;
    wt[1] = w1 - 3.0f * w3;
    wt[2] = 2.0f * w2;
    wt[3] = 4.0f * w3;
    #pragma unroll
    for (int t = 0; t < 4; t++) {
        __nv_bfloat16 hi = __float2bfloat16(wt[t]);
        __nv_bfloat16 lo = __float2bfloat16(wt[t] - __bfloat162float(hi));
        __nv_bfloat16* p = dst + (size_t)t * W_TERM + n * WK_STRIDE + k;
        p[0] = hi;
        p[W_HALF] = lo;
    }
}

__global__ void k_wconv1(const float* __restrict__ W) {
    int idx = threadIdx.x + blockIdx.x * blockDim.x;   // 384
    if (idx >= 384) return;
    float w0 = W[idx], w1 = W[idx + 384], w2 = W[idx + 768], w3 = W[idx + 1152];
    g_W1t[idx]        = w0 - w2;
    g_W1t[idx + 384]  = w1 - 3.0f * w3;
    g_W1t[idx + 768]  = 2.0f * w2;
    g_W1t[idx + 1152] = 4.0f * w3;
}

// ================= propagation =================
// prop A: fp32 source (g_acc) with BN fold, fp16 dest.  T1 = BN-fold(L @ acc)
__global__ void k_prop_a(const float* __restrict__ src, __half* __restrict__ out) {
    int gw = (blockIdx.x * blockDim.x + threadIdx.x) >> 5;
    int lane = threadIdx.x & 31;
    if (gw >= NN) return;
    float4 sc = *(const float4*)&g_bnsc[lane * 4];
    float4 sh = *(const float4*)&g_bnsh[lane * 4];
    int beg = g_rowptr[gw], end = g_rowptr[gw + 1];
    float ax = 0.f, ay = 0.f, az = 0.f, aw = 0.f, ws = 0.f;
    for (int e = beg; e < end; e++) {
        int2 cw = __ldg(&g_colw[e]);
        float w = __int_as_float(cw.y);
        float4 v = *(const float4*)&src[(size_t)cw.x * HH + lane * 4];
        ax += w * v.x; ay += w * v.y; az += w * v.z; aw += w * v.w;
        ws += w;
    }
    ax = sc.x * ax + sh.x * ws;
    ay = sc.y * ay + sh.y * ws;
    az = sc.z * az + sh.z * ws;
    aw = sc.w * aw + sh.w * ws;
    __half2 o0 = __floats2half2_rn(ax, ay);
    __half2 o1 = __floats2half2_rn(az, aw);
    uint2 st;
    st.x = *(uint32_t*)&o0;
    st.y = *(uint32_t*)&o1;
    *(uint2*)&out[(size_t)gw * HH + lane * 4] = st;
}

// prop B: fp16 source, fp16 dest.  out = L @ src  (half the gather traffic)
__global__ void k_prop_b(const __half* __restrict__ src, __half* __restrict__ out) {
    int gw = (blockIdx.x * blockDim.x + threadIdx.x) >> 5;
    int lane = threadIdx.x & 31;
    if (gw >= NN) return;
    int beg = g_rowptr[gw], end = g_rowptr[gw + 1];
    float ax = 0.f, ay = 0.f, az = 0.f, aw = 0.f;
    for (int e = beg; e < end; e++) {
        int2 cw = __ldg(&g_colw[e]);
        float w = __int_as_float(cw.y);
        uint2 raw = __ldg((const uint2*)&src[(size_t)cw.x * HH + lane * 4]);
        float2 f0 = __half22float2(*(__half2*)&raw.x);
        float2 f1 = __half22float2(*(__half2*)&raw.y);
        ax += w * f0.x; ay += w * f0.y; az += w * f1.x; aw += w * f1.y;
    }
    __half2 o0 = __floats2half2_rn(ax, ay);
    __half2 o1 = __floats2half2_rn(az, aw);
    uint2 st;
    st.x = *(uint32_t*)&o0;
    st.y = *(uint32_t*)&o1;
    *(uint2*)&out[(size_t)gw * HH + lane * 4] = st;
}

__global__ void k_prop3(const float* __restrict__ t, float* __restrict__ out) {
    int i = blockIdx.x * blockDim.x + threadIdx.x;
    if (i >= NN) return;
    int beg = g_rowptr[i], end = g_rowptr[i + 1];
    float a0 = 0.f, a1 = 0.f, a2 = 0.f;
    for (int e = beg; e < end; e++) {
        int2 cw = g_colw[e];
        float w = __int_as_float(cw.y);
        a0 += w * t[cw.x * 3 + 0];
        a1 += w * t[cw.x * 3 + 1];
        a2 += w * t[cw.x * 3 + 2];
    }
    out[i * 3 + 0] = a0;
    out[i * 3 + 1] = a1;
    out[i * 3 + 2] = a2;
}

// ================= layer 1 (3->128) SIMT, monomial weights, stats fused ==========
#define L1_ROWS 64
__global__ void k_layer1(const float* __restrict__ x, const float* __restrict__ b1) {
    __shared__ float w[4 * 3 * HH];
    __shared__ float bb[HH];
    for (int i = threadIdx.x; i < 4 * 3 * HH; i += blockDim.x) w[i] = g_W1t[i];
    if (threadIdx.x < HH) bb[threadIdx.x] = b1[threadIdx.x];
    __syncthreads();
    int h = threadIdx.x;
    int row0 = blockIdx.x * L1_ROWS;
    float s = 0.f, sq = 0.f;
    for (int r = 0; r < L1_ROWS; r++) {
        int i = row0 + r;
        if (i >= NN) break;
        float acc = bb[h];
        #pragma unroll
        for (int c = 0; c < 3; c++) {
            acc += x[i * 3 + c]    * w[(0 * 3 + c) * HH + h];
            acc += g_q1[i * 3 + c] * w[(1 * 3 + c) * HH + h];
            acc += g_q2[i * 3 + c] * w[(2 * 3 + c) * HH + h];
            acc += g_q3[i * 3 + c] * w[(3 * 3 + c) * HH + h];
        }
        float y = (acc > 0.f) ? acc : 0.01f * acc;
        g_acc[(size_t)i * HH + h] = y;
        s += y; sq += y * y;
    }
    atomicAdd(&g_sum[h], s);
    atomicAdd(&g_sumsq[h], sq);
}

// ================= BN finalize =================
__global__ void k_bnfin(const float* __restrict__ gam, const float* __restrict__ bet) {
    int h = threadIdx.x;
    float m = g_sum[h] * (1.0f / NN);
    float v = g_sumsq[h] * (1.0f / NN) - m * m;
    float r = rsqrtf(v + 1e-5f);
    float sc = gam[h] * r;
    g_bnsc[h] = sc;
    g_bnsh[h] = bet[h] - m * sc;
    g_sum[h] = 0.f;
    g_sumsq[h] = 0.f;
}

// ================= mma.sync split-bf16 4-term GEMM, cp.async B double-buffer =====
// C = act( BN(T0)@W~0 + T1@W~1 + T2@W~2 + T3@W~3 + bias ); T1..T3 are fp16.
#define SM_AHI 0
#define SM_ALO (SM_AHI + W_HALF)
#define SM_B0  (SM_ALO + W_HALF)
#define SM_B1  (SM_B0 + W_TERM)
#define SMEM_BF ((size_t)(SM_B1 + W_TERM))    // 104448 bf16
#define SMEM_BYTES (SMEM_BF * 2)              // 208896 bytes

__global__ void __launch_bounds__(256, 1)
k_mgemm(const float* __restrict__ T0, const __half* __restrict__ T1h,
        const __half* __restrict__ T2h, const __half* __restrict__ T3h,
        const __nv_bfloat16* __restrict__ Wc,
        float* __restrict__ C, const float* __restrict__ bias, float slope) {
    extern __shared__ __nv_bfloat16 sm[];
    int tid = threadIdx.x;
    int wid = tid >> 5, lane = tid & 31;
    int gid = lane >> 2, qid = lane & 3;
    int wm = wid & 3, wn = wid >> 2;
    int row0 = blockIdx.x * 128;
    uint32_t sb = smem_u32(sm);

    float acc[2][8][4];
    #pragma unroll
    for (int i = 0; i < 2; i++)
        #pragma unroll
        for (int j = 0; j < 8; j++)
            #pragma unroll
            for (int q = 0; q < 4; q++) acc[i][j][q] = 0.f;

    // prefetch B(0)
    {
        const char* src = (const char*)(Wc);
        uint32_t dst = sb + SM_B0 * 2;
        for (int q = tid; q < 4352; q += 256)
            cp_async16(dst + q * 16, src + q * 16);
        CP_COMMIT();
    }

    const __half* Th[4] = {(const __half*)0, T1h, T2h, T3h};
    for (int t = 0; t < 4; t++) {
        // --- stage A(t): term 0 fp32+BN fold; terms 1-3 fp16 ---
        for (int q = tid; q < 4096; q += 256) {
            int r = q >> 5;
            int c = (q & 31) << 2;
            int gi = row0 + r;
            float4 v = make_float4(0.f, 0.f, 0.f, 0.f);
            if (t == 0) {
                if (gi < NN) v = *(const float4*)&T0[(size_t)gi * HH + c];
                float4 s4 = *(const float4*)&g_bnsc[c];
                float4 h4 = *(const float4*)&g_bnsh[c];
                v.x = v.x * s4.x + h4.x; v.y = v.y * s4.y + h4.y;
                v.z = v.z * s4.z + h4.z; v.w = v.w * s4.w + h4.w;
            } else if (gi < NN) {
                uint2 raw = *(const uint2*)&Th[t][(size_t)gi * HH + c];
                float2 f0 = __half22float2(*(__half2*)&raw.x);
                float2 f1 = __half22float2(*(__half2*)&raw.y);
                v = make_float4(f0.x, f0.y, f1.x, f1.y);
            }
            __nv_bfloat16 hx = __float2bfloat16(v.x), hy = __float2bfloat16(v.y);
            __nv_bfloat16 hz = __float2bfloat16(v.z), hw = __float2bfloat16(v.w);
            int o = r * WK_STRIDE + c;
            sm[SM_AHI + o + 0] = hx; sm[SM_AHI + o + 1] = hy;
            sm[SM_AHI + o + 2] = hz; sm[SM_AHI + o + 3] = hw;
            sm[SM_ALO + o + 0] = __float2bfloat16(v.x - __bfloat162float(hx));
            sm[SM_ALO + o + 1] = __float2bfloat16(v.y - __bfloat162float(hy));
            sm[SM_ALO + o + 2] = __float2bfloat16(v.z - __bfloat162float(hz));
            sm[SM_ALO + o + 3] = __float2bfloat16(v.w - __bfloat162float(hw));
        }
        // --- prefetch B(t+1) into alternate buffer ---
        if (t < 3) {
            const char* src = (const char*)(Wc + (size_t)(t + 1) * W_TERM);
            uint32_t dst = sb + (((t + 1) & 1) ? SM_B1 : SM_B0) * 2;
            for (int q = tid; q < 4352; q += 256)
                cp_async16(dst + q * 16, src + q * 16);
            CP_COMMIT();
            CP_WAIT(1);
        } else {
            CP_WAIT(0);
        }
        __syncthreads();

        const __nv_bfloat16* Bbuf = sm + ((t & 1) ? SM_B1 : SM_B0);
        #pragma unroll
        for (int pass = 0; pass < 3; pass++) {
            const __nv_bfloat16* Ab = sm + ((pass == 2) ? SM_ALO : SM_AHI);
            const __nv_bfloat16* Bb = Bbuf + ((pass == 1) ? W_HALF : 0);
            #pragma unroll
            for (int ks = 0; ks < 8; ks++) {
                int k0 = ks * 16;
                uint32_t a[2][4];
                #pragma unroll
                for (int mt = 0; mt < 2; mt++) {
                    int r = wm * 32 + mt * 16 + gid;
                    a[mt][0] = *(const uint32_t*)&Ab[(r    ) * WK_STRIDE + k0     + qid * 2];
                    a[mt][1] = *(const uint32_t*)&Ab[(r + 8) * WK_STRIDE + k0     + qid * 2];
                    a[mt][2] = *(const uint32_t*)&Ab[(r    ) * WK_STRIDE + k0 + 8 + qid * 2];
                    a[mt][3] = *(const uint32_t*)&Ab[(r + 8) * WK_STRIDE + k0 + 8 + qid * 2];
                }
                #pragma unroll
                for (int nt = 0; nt < 8; nt++) {
                    int n = wn * 64 + nt * 8 + gid;
                    uint32_t b0 = *(const uint32_t*)&Bb[n * WK_STRIDE + k0     + qid * 2];
                    uint32_t b1 = *(const uint32_t*)&Bb[n * WK_STRIDE + k0 + 8 + qid * 2];
                    mma16816(acc[0][nt], a[0], b0, b1);
                    mma16816(acc[1][nt], a[1], b0, b1);
                }
            }
        }
        __syncthreads();
    }

    // --- epilogue: bias + activation + fused BN stats ---
    float* ssum = (float*)sm;
    if (bias) {
        ssum[tid] = 0.f;
        __syncthreads();
    }
    float scol[8][2], sqcol[8][2];
    #pragma unroll
    for (int nt = 0; nt < 8; nt++) {
        scol[nt][0] = 0.f; scol[nt][1] = 0.f;
        sqcol[nt][0] = 0.f; sqcol[nt][1] = 0.f;
    }
    #pragma unroll
    for (int mt = 0; mt < 2; mt++) {
        int r0 = row0 + wm * 32 + mt * 16 + gid;
        #pragma unroll
        for (int nt = 0; nt < 8; nt++) {
            int col = wn * 64 + nt * 8 + qid * 2;
            float c0 = acc[mt][nt][0], c1 = acc[mt][nt][1];
            float c2 = acc[mt][nt][2], c3 = acc[mt][nt][3];
            if (bias) {
                float bv0 = bias[col], bv1 = bias[col + 1];
                c0 += bv0; c0 = (c0 > 0.f) ? c0 : slope * c0;
                c1 += bv1; c1 = (c1 > 0.f) ? c1 : slope * c1;
                c2 += bv0; c2 = (c2 > 0.f) ? c2 : slope * c2;
                c3 += bv1; c3 = (c3 > 0.f) ? c3 : slope * c3;
                if (r0 < NN) {
                    scol[nt][0] += c0; sqcol[nt][0] += c0 * c0;
                    scol[nt][1] += c1; sqcol[nt][1] += c1 * c1;
                }
                if (r0 + 8 < NN) {
                    scol[nt][0] += c2; sqcol[nt][0] += c2 * c2;
                    scol[nt][1] += c3; sqcol[nt][1] += c3 * c3;
                }
            }
            if (r0 < NN)     *(float2*)&C[(size_t)r0 * HH + col]       = make_float2(c0, c1);
            if (r0 + 8 < NN) *(float2*)&C[(size_t)(r0 + 8) * HH + col] = make_float2(c2, c3);
        }
    }
    if (bias) {
        #pragma unroll
        for (int nt = 0; nt < 8; nt++) {
            #pragma unroll
            for (int j = 0; j < 2; j++) {
                float s = scol[nt][j], q = sqcol[nt][j];
                #pragma unroll
                for (int off = 4; off < 32; off <<= 1) {
                    s += __shfl_xor_sync(0xFFFFFFFFu, s, off);
                    q += __shfl_xor_sync(0xFFFFFFFFu, q, off);
                }
                if (lane < 4) {
                    int col = wn * 64 + nt * 8 + qid * 2 + j;
                    atomicAdd(&ssum[col], s);
                    atomicAdd(&ssum[128 + col], q);
                }
            }
        }
        __syncthreads();
        if (tid < 128) atomicAdd(&g_sum[tid], ssum[tid]);
        else           atomicAdd(&g_sumsq[tid - 128], ssum[tid]);
    }
}

// ================= final: +b4, L2-normalize, project 128->3 =================
__global__ void k_final(const float* __restrict__ b4, const float* __restrict__ Wm,
                        const float* __restrict__ bm, float* __restrict__ out) {
    __shared__ float wm[HH * 3];
    __shared__ float bb[HH];
    __shared__ float bmv[3];
    for (int i = threadIdx.x; i < HH * 3; i += blockDim.x) wm[i] = Wm[i];
    if (threadIdx.x < HH) bb[threadIdx.x] = b4[threadIdx.x];
    if (threadIdx.x < 3) bmv[threadIdx.x] = bm[threadIdx.x];
    __syncthreads();
    int gw = (blockIdx.x * blockDim.x + threadIdx.x) >> 5;
    int lane = threadIdx.x & 31;
    if (gw >= NN) return;
    float4 v = *(const float4*)&g_acc[(size_t)gw * HH + lane * 4];
    v.x += bb[lane * 4 + 0]; v.y += bb[lane * 4 + 1];
    v.z += bb[lane * 4 + 2]; v.w += bb[lane * 4 + 3];
    float sq = v.x * v.x + v.y * v.y + v.z * v.z + v.w * v.w;
    #pragma unroll
    for (int off = 16; off; off >>= 1) sq += __shfl_xor_sync(0xFFFFFFFFu, sq, off);
    float inv = 1.0f / fmaxf(sqrtf(sq), 1e-12f);
    v.x *= inv; v.y *= inv; v.z *= inv; v.w *= inv;
    float o0 = 0.f, o1 = 0.f, o2 = 0.f;
    float vv[4] = {v.x, v.y, v.z, v.w};
    #pragma unroll
    for (int t = 0; t < 4; t++) {
        int h = lane * 4 + t;
        o0 += vv[t] * wm[h * 3 + 0];
        o1 += vv[t] * wm[h * 3 + 1];
        o2 += vv[t] * wm[h * 3 + 2];
    }
    #pragma unroll
    for (int off = 16; off; off >>= 1) {
        o0 += __shfl_xor_sync(0xFFFFFFFFu, o0, off);
        o1 += __shfl_xor_sync(0xFFFFFFFFu, o1, off);
        o2 += __shfl_xor_sync(0xFFFFFFFFu, o2, off);
    }
    if (lane == 0) {
        out[gw * 3 + 0] = o0 + bmv[0];
        out[gw * 3 + 1] = o1 + bmv[1];
        out[gw * 3 + 2] = o2 + bmv[2];
    }
}

// ================= host =================
static inline int GB(long long n, int b) { return (int)((n + b - 1) / b); }

extern "C" void kernel_launch(void* const* d_in, const int* in_sizes, int n_in,
                              void* d_out, int out_size) {
    const float* x   = (const float*)d_in[0];
    const int*   ei  = (const int*)  d_in[1];
    const float* W1  = (const float*)d_in[2];  const float* b1  = (const float*)d_in[3];
    const float* W2  = (const float*)d_in[4];  const float* b2  = (const float*)d_in[5];
    const float* W3  = (const float*)d_in[6];  const float* b3  = (const float*)d_in[7];
    const float* W4  = (const float*)d_in[8];  const float* b4  = (const float*)d_in[9];
    const float* gm1 = (const float*)d_in[10]; const float* be1 = (const float*)d_in[11];
    const float* gm2 = (const float*)d_in[12]; const float* be2 = (const float*)d_in[13];
    const float* gm3 = (const float*)d_in[14]; const float* be3 = (const float*)d_in[15];
    const float* Wm  = (const float*)d_in[16]; const float* bm  = (const float*)d_in[17];
    float* out = (float*)d_out;

    float *p_acc, *p_q1, *p_q2, *p_q3;
    __half *p_T1h, *p_T2h, *p_T3h;
    __nv_bfloat16* p_Wc;
    cudaGetSymbolAddress((void**)&p_T1h, g_T1h);
    cudaGetSymbolAddress((void**)&p_T2h, g_T2h);
    cudaGetSymbolAddress((void**)&p_T3h, g_T3h);
    cudaGetSymbolAddress((void**)&p_acc, g_acc);
    cudaGetSymbolAddress((void**)&p_q1,  g_q1);
    cudaGetSymbolAddress((void**)&p_q2,  g_q2);
    cudaGetSymbolAddress((void**)&p_q3,  g_q3);
    cudaGetSymbolAddress((void**)&p_Wc,  g_Wc);

    cudaFuncSetAttribute(k_mgemm, cudaFuncAttributeMaxDynamicSharedMemorySize,
                         (int)SMEM_BYTES);

    // --- graph setup + weight transforms ---
    k_zero   <<<GB(NN, 256), 256>>>();
    k_degree <<<GB(EE, 256), 256>>>(ei);
    k_dinv   <<<GB(NN, 256), 256>>>();
    k_bsum   <<<NSCB, SCB>>>();
    k_bscan  <<<1, 1>>>();
    k_scanfin<<<NSCB, SCB>>>();
    k_scatter<<<GB(EE, 256), 256>>>(ei);
    k_wconv  <<<GB(16384, 256), 256>>>(W2, p_Wc);
    k_wconv  <<<GB(16384, 256), 256>>>(W3, p_Wc + W_LAYER);
    k_wconv  <<<GB(16384, 256), 256>>>(W4, p_Wc + 2 * W_LAYER);
    k_wconv1 <<<2, 192>>>(W1);

    // --- layer 1 (3 -> 128): monomial basis L^k x, leaky_relu, fused stats ---
    k_prop3<<<GB(NN, 256), 256>>>(x,    p_q1);
    k_prop3<<<GB(NN, 256), 256>>>(p_q1, p_q2);
    k_prop3<<<GB(NN, 256), 256>>>(p_q2, p_q3);
    k_layer1<<<GB(NN, L1_ROWS), 128>>>(x, b1);
    k_bnfin<<<1, 128>>>(gm1, be1);

    const int propBlocks = GB((long long)NN * 32, 256);
    const int gemmBlocks = GB(NN, 128);

    // --- layer 2 (128 -> 128), leaky_relu + BN ---
    k_prop_a<<<propBlocks, 256>>>(p_acc, p_T1h);
    k_prop_b<<<propBlocks, 256>>>(p_T1h, p_T2h);
    k_prop_b<<<propBlocks, 256>>>(p_T2h, p_T3h);
    k_mgemm<<<gemmBlocks, 256, SMEM_BYTES>>>(p_acc, p_T1h, p_T2h, p_T3h, p_Wc, p_acc, b2, 0.01f);
    k_bnfin<<<1, 128>>>(gm2, be2);

    // --- layer 3 (128 -> 128), relu + BN ---
    k_prop_a<<<propBlocks, 256>>>(p_acc, p_T1h);
    k_prop_b<<<propBlocks, 256>>>(p_T1h, p_T2h);
    k_prop_b<<<propBlocks, 256>>>(p_T2h, p_T3h);
    k_mgemm<<<gemmBlocks, 256, SMEM_BYTES>>>(p_acc, p_T1h, p_T2h, p_T3h, p_Wc + W_LAYER, p_acc, b3, 0.0f);
    k_bnfin<<<1, 128>>>(gm3, be3);

    // --- layer 4 (128 -> 128), then normalize + project ---
    k_prop_a<<<propBlocks, 256>>>(p_acc, p_T1h);
    k_prop_b<<<propBlocks, 256>>>(p_T1h, p_T2h);
    k_prop_b<<<propBlocks, 256>>>(p_T2h, p_T3h);
    k_mgemm<<<gemmBlocks, 256, SMEM_BYTES>>>(p_acc, p_T1h, p_T2h, p_T3h, p_Wc + 2 * W_LAYER, p_acc,
                                             (const float*)nullptr, 0.0f);
    k_final<<<GB((long long)NN * 32, 256), 256>>>(b4, Wm, bm, out);
}